// round 7
// baseline (speedup 1.0000x reference)
#include <cuda_runtime.h>
#include <cstdint>
#include <math.h>

#define NTOK 8192
#define CDIM 1024
#define CR   256
#define NADP 10
#define HWSZ 4096
#define BBAT 2
#define NANCH 3

// ---------------- scratch (static device globals: allocation-free) ----------------
static __device__ float g_norm[(long)NTOK * CDIM];          // [tok][c], tf32-rounded
static __device__ float g_w1t[(long)NADP * CR * CDIM];      // [a][d][c] (B^T, ln_scale folded, tf32)
static __device__ float g_w2t[(long)NADP * CDIM * CR];      // [a][n][k] (B^T, tf32)
static __device__ float g_bias1[NADP * CR];
static __device__ float g_bpart[32][NADP * CR];
static __device__ float g_h[(long)NADP * NTOK * CR];        // [a][slot][d] compacted
static __device__ float g_outall[(long)NADP * NTOK * CDIM]; // [a][slot][c] compacted
static __device__ int   g_cnt[NADP];
static __device__ int   g_toklist[NADP * NTOK];
static __device__ int   g_slot[NADP * NTOK];
static __device__ float g_mean[NTOK];
static __device__ float g_rstd[NTOK];

// ---------------- helpers ----------------
__device__ __forceinline__ float to_tf32(float x) {
    uint32_t o; asm("cvt.rna.tf32.f32 %0, %1;" : "=r"(o) : "f"(x));
    return __uint_as_float(o);
}
__device__ __forceinline__ void mma_tf32(float* d, uint32_t a0, uint32_t a1, uint32_t a2, uint32_t a3,
                                         uint32_t b0, uint32_t b1) {
    asm volatile("mma.sync.aligned.m16n8k8.row.col.f32.tf32.tf32.f32 "
        "{%0,%1,%2,%3}, {%4,%5,%6,%7}, {%8,%9}, {%0,%1,%2,%3};"
        : "+f"(d[0]), "+f"(d[1]), "+f"(d[2]), "+f"(d[3])
        : "r"(a0), "r"(a1), "r"(a2), "r"(a3), "r"(b0), "r"(b1));
}
__device__ __forceinline__ float gelu_exact(float x) {
    return 0.5f * x * (1.0f + erff(x * 0.70710678118654752440f));
}
__device__ __forceinline__ int adapter_idx(float v) {
    int idx = 0;
    idx += v > (1.0f / 9.0f);
    idx += v > (1.0f / 7.0f);
    idx += v > (1.0f / 5.0f);
    idx += v > (1.0f / 3.0f);
    idx += v > 1.0f;
    idx += v > 3.0f;
    idx += v > 5.0f;
    idx += v > 7.0f;
    idx += v > 9.0f;
    return idx;
}

// ---------------- compaction ----------------
__global__ void zero_cnt_kernel() {
    if (threadIdx.x < NADP) g_cnt[threadIdx.x] = 0;
}
__global__ void compact_kernel(const float* __restrict__ ar) {
    int tok = blockIdx.x * 256 + threadIdx.x;
    if (tok >= NTOK) return;
    int b = tok >> 12, p = tok & (HWSZ - 1);
    int ids[NANCH];
#pragma unroll
    for (int na = 0; na < NANCH; na++)
        ids[na] = adapter_idx(ar[(long)(b * NANCH + na) * HWSZ + p]);
#pragma unroll
    for (int na = 0; na < NANCH; na++) {
        bool dup = false;
#pragma unroll
        for (int j = 0; j < NANCH; j++) if (j < na) dup |= (ids[j] == ids[na]);
        if (!dup) {
            int a = ids[na];
            int s = atomicAdd(&g_cnt[a], 1);
            g_toklist[a * NTOK + s] = tok;
            g_slot[a * NTOK + tok] = s;
        }
    }
}

// ---------------- weight prep ----------------
__global__ void prep_w1_kernel(const float* __restrict__ ln_scale, const float* __restrict__ w1) {
    __shared__ float t[32][33];
    int a = blockIdx.z, c0 = blockIdx.x * 32, d0 = blockIdx.y * 32;
    int tx = threadIdx.x, ty = threadIdx.y;
#pragma unroll
    for (int jj = 0; jj < 4; jj++) {
        int ci = ty + jj * 8;
        t[ci][tx] = w1[((long)a * CDIM + c0 + ci) * CR + d0 + tx] * ln_scale[a * CDIM + c0 + ci];
    }
    __syncthreads();
#pragma unroll
    for (int jj = 0; jj < 4; jj++) {
        int di = ty + jj * 8;
        g_w1t[((long)a * CR + d0 + di) * CDIM + c0 + tx] = to_tf32(t[tx][di]);
    }
}
__global__ void prep_w2_kernel(const float* __restrict__ w2) {
    __shared__ float t[32][33];
    int a = blockIdx.z, n0 = blockIdx.x * 32, k0 = blockIdx.y * 32;
    int tx = threadIdx.x, ty = threadIdx.y;
#pragma unroll
    for (int jj = 0; jj < 4; jj++) {
        int ki = ty + jj * 8;
        t[ki][tx] = w2[((long)a * CR + k0 + ki) * CDIM + n0 + tx];
    }
    __syncthreads();
#pragma unroll
    for (int jj = 0; jj < 4; jj++) {
        int ni = ty + jj * 8;
        g_w2t[((long)a * CDIM + n0 + ni) * CR + k0 + tx] = to_tf32(t[tx][ni]);
    }
}
// bias1[a][d] = sum_c ln_bias[a][c] * w1[a][c][d]  (2-stage, deterministic order)
__global__ void fold_bias_part(const float* __restrict__ ln_bias, const float* __restrict__ w1) {
    int a = blockIdx.x, ch = blockIdx.y, d = threadIdx.x;
    const float* wb = w1 + (long)a * CDIM * CR + (long)ch * 32 * CR;
    const float* lb = ln_bias + a * CDIM + ch * 32;
    float s = 0.f;
#pragma unroll
    for (int c = 0; c < 32; c++) s = fmaf(lb[c], wb[(long)c * CR + d], s);
    g_bpart[ch][a * CR + d] = s;
}
__global__ void fold_bias_reduce() {
    int i = blockIdx.x * 256 + threadIdx.x;
    if (i >= NADP * CR) return;
    float s = 0.f;
#pragma unroll
    for (int ch = 0; ch < 32; ch++) s += g_bpart[ch][i];
    g_bias1[i] = s;
}

// ---------------- LayerNorm pass 1: per-token stats (coalesced, full-chip) ----------------
__global__ void ln_stats_kernel(const float* __restrict__ feat) {
    int b  = blockIdx.y;
    int p0 = blockIdx.x * 32;
    int tx = threadIdx.x, ty = threadIdx.y;
    const float* base = feat + (long)b * CDIM * HWSZ + p0 + tx;
    float s = 0.f, sq = 0.f;
#pragma unroll 16
    for (int c = ty; c < CDIM; c += 8) {
        float v = base[(long)c * HWSZ];
        s += v; sq = fmaf(v, v, sq);
    }
    __shared__ float ss[8][33], qq[8][33];
    ss[ty][tx] = s; qq[ty][tx] = sq;
    __syncthreads();
    if (ty == 0) {
        float S = 0.f, Q = 0.f;
#pragma unroll
        for (int j = 0; j < 8; j++) { S += ss[j][tx]; Q += qq[j][tx]; }
        float mean = S * (1.0f / CDIM);
        float var  = Q * (1.0f / CDIM) - mean * mean;
        int tok = b * HWSZ + p0 + tx;
        g_mean[tok] = mean;
        g_rstd[tok] = rsqrtf(var + 1e-5f);
    }
}

// ---------------- LayerNorm pass 2: normalize + transpose ----------------
__global__ void ln_apply_kernel(const float* __restrict__ feat) {
    __shared__ float t[32][33];
    int b  = blockIdx.z;
    int c0 = blockIdx.y * 32;
    int p0 = blockIdx.x * 32;
    int tx = threadIdx.x, ty = threadIdx.y;
#pragma unroll
    for (int cj = 0; cj < 4; cj++) {
        int ci = ty + cj * 8;
        t[ci][tx] = feat[((long)b * CDIM + c0 + ci) * HWSZ + p0 + tx];
    }
    __syncthreads();
#pragma unroll
    for (int pj = 0; pj < 4; pj++) {
        int pi = ty + pj * 8;
        int tok = b * HWSZ + p0 + pi;
        float mean = g_mean[tok], rstd = g_rstd[tok];
        g_norm[(long)tok * CDIM + c0 + tx] = to_tf32((t[tx][pi] - mean) * rstd);
    }
}

// ---------------- tf32 mma.sync GEMM on compacted rows ----------------
// CTA 128x128, BK=32, 8 warps (2M x 4N), warp tile 64x32, m16n8k8.
// Single 32KB SMEM buffer + register prefetch -> 2 CTAs/SM.
__device__ __forceinline__ int sts_base(int row, int q) {
    return row * 32 + (((((q & 1) << 4) | (q >> 1))) ^ (((row & 1) << 4) | ((row & 2) << 2)));
}

__global__ void __launch_bounds__(256, 2)
mma_gemm(const float* __restrict__ Ab, const float* __restrict__ Bb,
         const float* __restrict__ bias, float* __restrict__ Cb,
         const int* __restrict__ toklist,
         int K, int lda, int ldb, int ldc,
         long sA, long sB, long sC, int doGelu)
{
    extern __shared__ float sm[];
    int tid = threadIdx.x;
    int mB = blockIdx.x * 128, nB = blockIdx.y * 128, a = blockIdx.z;

    int cnt = g_cnt[a];
    if (mB >= cnt) return;

    const float* A = Ab + (long)a * sA;
    const float* B = Bb + (long)a * sB;
    float* C = Cb + (long)a * sC;
    const int* tl = toklist ? toklist + a * NTOK : nullptr;

    int lane = tid & 31, wid = tid >> 5;
    int wm0 = (wid & 1) * 64;
    int wn0 = (wid >> 1) * 32;
    int r = lane >> 2, c = lane & 3;
    int sws = ((r & 1) << 4) | ((r & 2) << 2);
    int lo_b = (c * 4) ^ sws;
    int hi_b = (16 + c * 4) ^ sws;

    int q = tid & 7;
    int row0 = tid >> 3;

    const float* Arow[4];
    const float* Brow[4];
#pragma unroll
    for (int rr = 0; rr < 4; rr++) {
        int m = mB + row0 + rr * 32;
        int mc = m < cnt ? m : (cnt - 1);
        long arow = tl ? (long)tl[mc] : (long)mc;
        Arow[rr] = A + arow * lda;
        Brow[rr] = B + (long)(nB + row0 + rr * 32) * ldb;
    }

    float acc[4][4][4];
#pragma unroll
    for (int t = 0; t < 4; t++)
#pragma unroll
        for (int u = 0; u < 4; u++)
#pragma unroll
            for (int e = 0; e < 4; e++) acc[t][u][e] = 0.f;

    int nkt = K >> 5;
    float4 ra[4], rb[4];

    float* As = sm;
    float* Bs = sm + 4096;

    // prologue: tile 0 -> regs -> smem; tile 1 -> regs
#pragma unroll
    for (int rr = 0; rr < 4; rr++) {
        ra[rr] = *(const float4*)(Arow[rr] + q * 4);
        rb[rr] = *(const float4*)(Brow[rr] + q * 4);
    }
#pragma unroll
    for (int rr = 0; rr < 4; rr++) {
        int row = row0 + rr * 32;
        int b0 = sts_base(row, q);
        As[b0 ^ 0] = ra[rr].x; As[b0 ^ 4] = ra[rr].y; As[b0 ^ 8] = ra[rr].z; As[b0 ^ 12] = ra[rr].w;
        Bs[b0 ^ 0] = rb[rr].x; Bs[b0 ^ 4] = rb[rr].y; Bs[b0 ^ 8] = rb[rr].z; Bs[b0 ^ 12] = rb[rr].w;
    }
    if (nkt > 1) {
#pragma unroll
        for (int rr = 0; rr < 4; rr++) {
            ra[rr] = *(const float4*)(Arow[rr] + 32 + q * 4);
            rb[rr] = *(const float4*)(Brow[rr] + 32 + q * 4);
        }
    }
    __syncthreads();

    for (int kt = 0; kt < nkt; kt++) {
        // compute on the single smem buffer
        {
            float bl[4][4], bh[4][4];
#pragma unroll
            for (int u = 0; u < 4; u++) {
                int n = wn0 + u * 8 + r;
                float4 v0 = *(const float4*)(Bs + n * 32 + lo_b);
                float4 v1 = *(const float4*)(Bs + n * 32 + hi_b);
                bl[u][0] = v0.x; bl[u][1] = v0.y; bl[u][2] = v0.z; bl[u][3] = v0.w;
                bh[u][0] = v1.x; bh[u][1] = v1.y; bh[u][2] = v1.z; bh[u][3] = v1.w;
            }
#pragma unroll
            for (int t = 0; t < 4; t++) {
                int m0 = wm0 + t * 16 + r;
                float al0[4], ah0[4], al1[4], ah1[4];
                float4 v;
                v = *(const float4*)(As + m0 * 32 + lo_b);       al0[0]=v.x; al0[1]=v.y; al0[2]=v.z; al0[3]=v.w;
                v = *(const float4*)(As + m0 * 32 + hi_b);       ah0[0]=v.x; ah0[1]=v.y; ah0[2]=v.z; ah0[3]=v.w;
                v = *(const float4*)(As + (m0 + 8) * 32 + lo_b); al1[0]=v.x; al1[1]=v.y; al1[2]=v.z; al1[3]=v.w;
                v = *(const float4*)(As + (m0 + 8) * 32 + hi_b); ah1[0]=v.x; ah1[1]=v.y; ah1[2]=v.z; ah1[3]=v.w;
#pragma unroll
                for (int j = 0; j < 4; j++) {
                    uint32_t a0 = __float_as_uint(al0[j]);
                    uint32_t a1 = __float_as_uint(al1[j]);
                    uint32_t a2 = __float_as_uint(ah0[j]);
                    uint32_t a3 = __float_as_uint(ah1[j]);
#pragma unroll
                    for (int u = 0; u < 4; u++)
                        mma_tf32(acc[t][u], a0, a1, a2, a3,
                                 __float_as_uint(bl[u][j]), __float_as_uint(bh[u][j]));
                }
            }
        }
        if (kt + 1 < nkt) {
            __syncthreads();   // everyone done reading tile kt
#pragma unroll
            for (int rr = 0; rr < 4; rr++) {
                int row = row0 + rr * 32;
                int b0 = sts_base(row, q);
                As[b0 ^ 0] = ra[rr].x; As[b0 ^ 4] = ra[rr].y; As[b0 ^ 8] = ra[rr].z; As[b0 ^ 12] = ra[rr].w;
                Bs[b0 ^ 0] = rb[rr].x; Bs[b0 ^ 4] = rb[rr].y; Bs[b0 ^ 8] = rb[rr].z; Bs[b0 ^ 12] = rb[rr].w;
            }
            if (kt + 2 < nkt) {
                int ko = (kt + 2) * 32;
#pragma unroll
                for (int rr = 0; rr < 4; rr++) {
                    ra[rr] = *(const float4*)(Arow[rr] + ko + q * 4);
                    rb[rr] = *(const float4*)(Brow[rr] + ko + q * 4);
                }
            }
            __syncthreads();   // tile kt+1 visible
        }
    }

    // ---- epilogue: store rows < cnt ----
#pragma unroll
    for (int t = 0; t < 4; t++) {
        int gr0 = mB + wm0 + t * 16 + r;
        int gr1 = gr0 + 8;
        bool k0 = gr0 < cnt;
        bool k1 = gr1 < cnt;
        if (!k0 && !k1) continue;
#pragma unroll
        for (int u = 0; u < 4; u++) {
            int col = nB + wn0 + u * 8 + c * 2;
            float v00 = acc[t][u][0], v01 = acc[t][u][1];
            float v10 = acc[t][u][2], v11 = acc[t][u][3];
            if (doGelu) {
                float b0v = bias[a * CR + col], b1v = bias[a * CR + col + 1];
                v00 = to_tf32(gelu_exact(v00 + b0v));
                v01 = to_tf32(gelu_exact(v01 + b1v));
                v10 = to_tf32(gelu_exact(v10 + b0v));
                v11 = to_tf32(gelu_exact(v11 + b1v));
            }
            if (k0) *(float2*)(C + (long)gr0 * ldc + col) = make_float2(v00, v01);
            if (k1) *(float2*)(C + (long)gr1 * ldc + col) = make_float2(v10, v11);
        }
    }
}

// ---------------- gather + mean + residual (NCHW) ----------------
__global__ void gather_kernel(const float* __restrict__ feat,
                              const float* __restrict__ ar,
                              float* __restrict__ out)
{
    int b  = blockIdx.z;
    int c0 = blockIdx.y * 32;
    int p0 = blockIdx.x * 32;
    int tx = threadIdx.x, ty = threadIdx.y;
    __shared__ float acc[32][33];
#pragma unroll
    for (int jj = 0; jj < 4; jj++) {
        int pi = ty + jj * 8;
        int p = p0 + pi;
        long tok = (long)b * HWSZ + p;
        float s = 0.f;
#pragma unroll
        for (int na = 0; na < NANCH; na++) {
            float v = ar[(long)(b * NANCH + na) * HWSZ + p];
            int a = adapter_idx(v);
            int slot = g_slot[a * NTOK + tok];
            s += g_outall[((long)a * NTOK + slot) * CDIM + c0 + tx];
        }
        acc[pi][tx] = s * (1.0f / 3.0f);
    }
    __syncthreads();
    int tid = ty * 32 + tx;
    int pi  = tid & 31;
    int ci0 = tid >> 5;
#pragma unroll
    for (int cj = 0; cj < 4; cj++) {
        int ci = ci0 + cj * 8;
        long off = (long)(b * CDIM + c0 + ci) * HWSZ + p0 + pi;
        out[off] = acc[pi][ci] + feat[off];
    }
}

// ---------------- launch ----------------
extern "C" void kernel_launch(void* const* d_in, const int* in_sizes, int n_in,
                              void* d_out, int out_size) {
    const float* feat     = (const float*)d_in[0];
    const float* ar       = (const float*)d_in[1];
    const float* ln_scale = (const float*)d_in[2];
    const float* ln_bias  = (const float*)d_in[3];
    const float* w1       = (const float*)d_in[4];
    const float* w2       = (const float*)d_in[5];
    float* out = (float*)d_out;

    float *norm, *w1t, *w2t, *bias1, *h, *outall;
    int *toklist;
    cudaGetSymbolAddress((void**)&norm,    g_norm);
    cudaGetSymbolAddress((void**)&w1t,     g_w1t);
    cudaGetSymbolAddress((void**)&w2t,     g_w2t);
    cudaGetSymbolAddress((void**)&bias1,   g_bias1);
    cudaGetSymbolAddress((void**)&h,       g_h);
    cudaGetSymbolAddress((void**)&outall,  g_outall);
    cudaGetSymbolAddress((void**)&toklist, g_toklist);

    static bool attr_set = false;
    if (!attr_set) {
        cudaFuncSetAttribute(mma_gemm, cudaFuncAttributeMaxDynamicSharedMemorySize, 32768);
        attr_set = true;
    }

    zero_cnt_kernel<<<1, 32>>>();
    compact_kernel<<<NTOK / 256, 256>>>(ar);
    prep_w1_kernel<<<dim3(CDIM / 32, CR / 32, NADP), dim3(32, 8)>>>(ln_scale, w1);
    prep_w2_kernel<<<dim3(CDIM / 32, CR / 32, NADP), dim3(32, 8)>>>(w2);
    fold_bias_part<<<dim3(NADP, 32), 256>>>(ln_bias, w1);
    fold_bias_reduce<<<(NADP * CR + 255) / 256, 256>>>();
    ln_stats_kernel<<<dim3(HWSZ / 32, BBAT), dim3(32, 8)>>>(feat);
    ln_apply_kernel<<<dim3(HWSZ / 32, CDIM / 32, BBAT), dim3(32, 8)>>>(feat);

    // GEMM1: h[a][slot] = gelu(norm[tok(slot)] @ w1t[a]^T + bias1[a])  N=256 K=1024
    mma_gemm<<<dim3(NTOK / 128, CR / 128, NADP), 256, 32768>>>(
        norm, w1t, bias1, h, toklist,
        CDIM, CDIM, CDIM, CR,
        0L, (long)CR * CDIM, (long)NTOK * CR, 1);

    // GEMM2: outall[a][slot] = h[a][slot] @ w2t[a]^T  N=1024 K=256
    mma_gemm<<<dim3(NTOK / 128, CDIM / 128, NADP), 256, 32768>>>(
        h, w2t, nullptr, outall, nullptr,
        CR, CR, CR, CDIM,
        (long)NTOK * CR, (long)CDIM * CR, (long)NTOK * CDIM, 0);

    gather_kernel<<<dim3(HWSZ / 32, CDIM / 32, BBAT), dim3(32, 8)>>>(feat, ar, out);
}

// round 8
// speedup vs baseline: 1.0818x; 1.0818x over previous
#include <cuda_runtime.h>
#include <cstdint>
#include <math.h>

#define NTOK 8192
#define CDIM 1024
#define CR   256
#define NADP 10
#define HWSZ 4096
#define BBAT 2
#define NANCH 3

// ---------------- scratch (static device globals: allocation-free) ----------------
static __device__ float g_norm[(long)NTOK * CDIM];          // [tok][c], tf32-rounded
static __device__ float g_w1t[(long)NADP * CR * CDIM];      // [a][d][c] (B^T, ln_scale folded, tf32)
static __device__ float g_w2t[(long)NADP * CDIM * CR];      // [a][n][k] (B^T, tf32)
static __device__ float g_bias1[NADP * CR];
static __device__ float g_bpart[32][NADP * CR];
static __device__ float g_h[(long)NADP * NTOK * CR];        // [a][slot][d] compacted
static __device__ float g_outall[(long)NADP * NTOK * CDIM]; // [a][slot][c] compacted
static __device__ int   g_cnt[NADP];
static __device__ int   g_toklist[NADP * NTOK];
static __device__ int   g_slot[NADP * NTOK];
static __device__ float g_mean[NTOK];
static __device__ float g_rstd[NTOK];

// ---------------- helpers ----------------
__device__ __forceinline__ float to_tf32(float x) {
    uint32_t o; asm("cvt.rna.tf32.f32 %0, %1;" : "=r"(o) : "f"(x));
    return __uint_as_float(o);
}
__device__ __forceinline__ void mma_tf32(float* d, uint32_t a0, uint32_t a1, uint32_t a2, uint32_t a3,
                                         uint32_t b0, uint32_t b1) {
    asm volatile("mma.sync.aligned.m16n8k8.row.col.f32.tf32.tf32.f32 "
        "{%0,%1,%2,%3}, {%4,%5,%6,%7}, {%8,%9}, {%0,%1,%2,%3};"
        : "+f"(d[0]), "+f"(d[1]), "+f"(d[2]), "+f"(d[3])
        : "r"(a0), "r"(a1), "r"(a2), "r"(a3), "r"(b0), "r"(b1));
}
__device__ __forceinline__ float gelu_exact(float x) {
    return 0.5f * x * (1.0f + erff(x * 0.70710678118654752440f));
}
__device__ __forceinline__ int adapter_idx(float v) {
    int idx = 0;
    idx += v > (1.0f / 9.0f);
    idx += v > (1.0f / 7.0f);
    idx += v > (1.0f / 5.0f);
    idx += v > (1.0f / 3.0f);
    idx += v > 1.0f;
    idx += v > 3.0f;
    idx += v > 5.0f;
    idx += v > 7.0f;
    idx += v > 9.0f;
    return idx;
}

// ---------------- compaction ----------------
__global__ void zero_cnt_kernel() {
    if (threadIdx.x < NADP) g_cnt[threadIdx.x] = 0;
}
__global__ void compact_kernel(const float* __restrict__ ar) {
    int tok = blockIdx.x * 256 + threadIdx.x;
    if (tok >= NTOK) return;
    int b = tok >> 12, p = tok & (HWSZ - 1);
    int ids[NANCH];
#pragma unroll
    for (int na = 0; na < NANCH; na++)
        ids[na] = adapter_idx(ar[(long)(b * NANCH + na) * HWSZ + p]);
#pragma unroll
    for (int na = 0; na < NANCH; na++) {
        bool dup = false;
#pragma unroll
        for (int j = 0; j < NANCH; j++) if (j < na) dup |= (ids[j] == ids[na]);
        if (!dup) {
            int a = ids[na];
            int s = atomicAdd(&g_cnt[a], 1);
            g_toklist[a * NTOK + s] = tok;
            g_slot[a * NTOK + tok] = s;
        }
    }
}

// ---------------- weight prep ----------------
__global__ void prep_w1_kernel(const float* __restrict__ ln_scale, const float* __restrict__ w1) {
    __shared__ float t[32][33];
    int a = blockIdx.z, c0 = blockIdx.x * 32, d0 = blockIdx.y * 32;
    int tx = threadIdx.x, ty = threadIdx.y;
#pragma unroll
    for (int jj = 0; jj < 4; jj++) {
        int ci = ty + jj * 8;
        t[ci][tx] = w1[((long)a * CDIM + c0 + ci) * CR + d0 + tx] * ln_scale[a * CDIM + c0 + ci];
    }
    __syncthreads();
#pragma unroll
    for (int jj = 0; jj < 4; jj++) {
        int di = ty + jj * 8;
        g_w1t[((long)a * CR + d0 + di) * CDIM + c0 + tx] = to_tf32(t[tx][di]);
    }
}
__global__ void prep_w2_kernel(const float* __restrict__ w2) {
    __shared__ float t[32][33];
    int a = blockIdx.z, n0 = blockIdx.x * 32, k0 = blockIdx.y * 32;
    int tx = threadIdx.x, ty = threadIdx.y;
#pragma unroll
    for (int jj = 0; jj < 4; jj++) {
        int ki = ty + jj * 8;
        t[ki][tx] = w2[((long)a * CR + k0 + ki) * CDIM + n0 + tx];
    }
    __syncthreads();
#pragma unroll
    for (int jj = 0; jj < 4; jj++) {
        int ni = ty + jj * 8;
        g_w2t[((long)a * CDIM + n0 + ni) * CR + k0 + tx] = to_tf32(t[tx][ni]);
    }
}
// bias1[a][d] = sum_c ln_bias[a][c] * w1[a][c][d]  (2-stage, deterministic order)
__global__ void fold_bias_part(const float* __restrict__ ln_bias, const float* __restrict__ w1) {
    int a = blockIdx.x, ch = blockIdx.y, d = threadIdx.x;
    const float* wb = w1 + (long)a * CDIM * CR + (long)ch * 32 * CR;
    const float* lb = ln_bias + a * CDIM + ch * 32;
    float s = 0.f;
#pragma unroll
    for (int c = 0; c < 32; c++) s = fmaf(lb[c], wb[(long)c * CR + d], s);
    g_bpart[ch][a * CR + d] = s;
}
__global__ void fold_bias_reduce() {
    int i = blockIdx.x * 256 + threadIdx.x;
    if (i >= NADP * CR) return;
    float s = 0.f;
#pragma unroll
    for (int ch = 0; ch < 32; ch++) s += g_bpart[ch][i];
    g_bias1[i] = s;
}

// ---------------- LayerNorm pass 1: per-token stats (coalesced, full-chip) ----------------
__global__ void ln_stats_kernel(const float* __restrict__ feat) {
    int b  = blockIdx.y;
    int p0 = blockIdx.x * 32;
    int tx = threadIdx.x, ty = threadIdx.y;
    const float* base = feat + (long)b * CDIM * HWSZ + p0 + tx;
    float s = 0.f, sq = 0.f;
#pragma unroll 16
    for (int c = ty; c < CDIM; c += 8) {
        float v = base[(long)c * HWSZ];
        s += v; sq = fmaf(v, v, sq);
    }
    __shared__ float ss[8][33], qq[8][33];
    ss[ty][tx] = s; qq[ty][tx] = sq;
    __syncthreads();
    if (ty == 0) {
        float S = 0.f, Q = 0.f;
#pragma unroll
        for (int j = 0; j < 8; j++) { S += ss[j][tx]; Q += qq[j][tx]; }
        float mean = S * (1.0f / CDIM);
        float var  = Q * (1.0f / CDIM) - mean * mean;
        int tok = b * HWSZ + p0 + tx;
        g_mean[tok] = mean;
        g_rstd[tok] = rsqrtf(var + 1e-5f);
    }
}

// ---------------- LayerNorm pass 2: normalize + transpose ----------------
__global__ void ln_apply_kernel(const float* __restrict__ feat) {
    __shared__ float t[32][33];
    int b  = blockIdx.z;
    int c0 = blockIdx.y * 32;
    int p0 = blockIdx.x * 32;
    int tx = threadIdx.x, ty = threadIdx.y;
#pragma unroll
    for (int cj = 0; cj < 4; cj++) {
        int ci = ty + cj * 8;
        t[ci][tx] = feat[((long)b * CDIM + c0 + ci) * HWSZ + p0 + tx];
    }
    __syncthreads();
#pragma unroll
    for (int pj = 0; pj < 4; pj++) {
        int pi = ty + pj * 8;
        int tok = b * HWSZ + p0 + pi;
        float mean = g_mean[tok], rstd = g_rstd[tok];
        g_norm[(long)tok * CDIM + c0 + tx] = to_tf32((t[tx][pi] - mean) * rstd);
    }
}

// ---------------- tf32 mma.sync GEMM on compacted rows ----------------
// CTA 128x128, BK=32, 512 threads = 16 warps (4M x 4N), warp tile 32x32.
// Double-buffered 64KB SMEM, register gmem prefetch. m16n8k8 frags.
__device__ __forceinline__ int sts_base(int row, int q) {
    return row * 32 + (((((q & 1) << 4) | (q >> 1))) ^ (((row & 1) << 4) | ((row & 2) << 2)));
}

__global__ void __launch_bounds__(512, 1)
mma_gemm(const float* __restrict__ Ab, const float* __restrict__ Bb,
         const float* __restrict__ bias, float* __restrict__ Cb,
         const int* __restrict__ toklist,
         int K, int lda, int ldb, int ldc,
         long sA, long sB, long sC, int doGelu)
{
    extern __shared__ float sm[];
    int tid = threadIdx.x;
    int mB = blockIdx.x * 128, nB = blockIdx.y * 128, a = blockIdx.z;

    int cnt = g_cnt[a];
    if (mB >= cnt) return;

    const float* A = Ab + (long)a * sA;
    const float* B = Bb + (long)a * sB;
    float* C = Cb + (long)a * sC;
    const int* tl = toklist ? toklist + a * NTOK : nullptr;

    int lane = tid & 31, wid = tid >> 5;
    int wm0 = (wid & 3) * 32;       // 4 M-warps
    int wn0 = (wid >> 2) * 32;      // 4 N-warps
    int r = lane >> 2, c = lane & 3;
    int sws = ((r & 1) << 4) | ((r & 2) << 2);
    int lo_b = (c * 4) ^ sws;
    int hi_b = (16 + c * 4) ^ sws;

    int q = tid & 7;
    int row0 = tid >> 3;            // 0..63; covers rows row0, row0+64

    const float* Arow[2];
    const float* Brow[2];
#pragma unroll
    for (int rr = 0; rr < 2; rr++) {
        int m = mB + row0 + rr * 64;
        int mc = m < cnt ? m : (cnt - 1);
        long arow = tl ? (long)tl[mc] : (long)mc;
        Arow[rr] = A + arow * lda;
        Brow[rr] = B + (long)(nB + row0 + rr * 64) * ldb;
    }

    float acc[2][4][4];
#pragma unroll
    for (int t = 0; t < 2; t++)
#pragma unroll
        for (int u = 0; u < 4; u++)
#pragma unroll
            for (int e = 0; e < 4; e++) acc[t][u][e] = 0.f;

    int nkt = K >> 5;
    float4 ra[2], rb[2];

    // prologue: tile 0 -> regs -> stage0; tile 1 -> regs
#pragma unroll
    for (int rr = 0; rr < 2; rr++) {
        ra[rr] = *(const float4*)(Arow[rr] + q * 4);
        rb[rr] = *(const float4*)(Brow[rr] + q * 4);
    }
    {
        float* As = sm;
        float* Bs = sm + 4096;
#pragma unroll
        for (int rr = 0; rr < 2; rr++) {
            int row = row0 + rr * 64;
            int b0 = sts_base(row, q);
            As[b0 ^ 0] = ra[rr].x; As[b0 ^ 4] = ra[rr].y; As[b0 ^ 8] = ra[rr].z; As[b0 ^ 12] = ra[rr].w;
            Bs[b0 ^ 0] = rb[rr].x; Bs[b0 ^ 4] = rb[rr].y; Bs[b0 ^ 8] = rb[rr].z; Bs[b0 ^ 12] = rb[rr].w;
        }
    }
    if (nkt > 1) {
#pragma unroll
        for (int rr = 0; rr < 2; rr++) {
            ra[rr] = *(const float4*)(Arow[rr] + 32 + q * 4);
            rb[rr] = *(const float4*)(Brow[rr] + 32 + q * 4);
        }
    }
    __syncthreads();

    for (int kt = 0; kt < nkt; kt++) {
        if (kt + 1 < nkt) {
            float* As = sm + ((kt + 1) & 1) * 8192;
            float* Bs = As + 4096;
#pragma unroll
            for (int rr = 0; rr < 2; rr++) {
                int row = row0 + rr * 64;
                int b0 = sts_base(row, q);
                As[b0 ^ 0] = ra[rr].x; As[b0 ^ 4] = ra[rr].y; As[b0 ^ 8] = ra[rr].z; As[b0 ^ 12] = ra[rr].w;
                Bs[b0 ^ 0] = rb[rr].x; Bs[b0 ^ 4] = rb[rr].y; Bs[b0 ^ 8] = rb[rr].z; Bs[b0 ^ 12] = rb[rr].w;
            }
        }
        if (kt + 2 < nkt) {
            int ko = (kt + 2) * 32;
#pragma unroll
            for (int rr = 0; rr < 2; rr++) {
                ra[rr] = *(const float4*)(Arow[rr] + ko + q * 4);
                rb[rr] = *(const float4*)(Brow[rr] + ko + q * 4);
            }
        }
        // compute on stage kt&1
        {
            const float* As = sm + (kt & 1) * 8192;
            const float* Bs = As + 4096;
            float bl[4][4], bh[4][4];
#pragma unroll
            for (int u = 0; u < 4; u++) {
                int n = wn0 + u * 8 + r;
                float4 v0 = *(const float4*)(Bs + n * 32 + lo_b);
                float4 v1 = *(const float4*)(Bs + n * 32 + hi_b);
                bl[u][0] = v0.x; bl[u][1] = v0.y; bl[u][2] = v0.z; bl[u][3] = v0.w;
                bh[u][0] = v1.x; bh[u][1] = v1.y; bh[u][2] = v1.z; bh[u][3] = v1.w;
            }
#pragma unroll
            for (int t = 0; t < 2; t++) {
                int m0 = wm0 + t * 16 + r;
                float al0[4], ah0[4], al1[4], ah1[4];
                float4 v;
                v = *(const float4*)(As + m0 * 32 + lo_b);       al0[0]=v.x; al0[1]=v.y; al0[2]=v.z; al0[3]=v.w;
                v = *(const float4*)(As + m0 * 32 + hi_b);       ah0[0]=v.x; ah0[1]=v.y; ah0[2]=v.z; ah0[3]=v.w;
                v = *(const float4*)(As + (m0 + 8) * 32 + lo_b); al1[0]=v.x; al1[1]=v.y; al1[2]=v.z; al1[3]=v.w;
                v = *(const float4*)(As + (m0 + 8) * 32 + hi_b); ah1[0]=v.x; ah1[1]=v.y; ah1[2]=v.z; ah1[3]=v.w;
#pragma unroll
                for (int j = 0; j < 4; j++) {
                    uint32_t a0 = __float_as_uint(al0[j]);
                    uint32_t a1 = __float_as_uint(al1[j]);
                    uint32_t a2 = __float_as_uint(ah0[j]);
                    uint32_t a3 = __float_as_uint(ah1[j]);
#pragma unroll
                    for (int u = 0; u < 4; u++)
                        mma_tf32(acc[t][u], a0, a1, a2, a3,
                                 __float_as_uint(bl[u][j]), __float_as_uint(bh[u][j]));
                }
            }
        }
        __syncthreads();
    }

    // ---- epilogue: store rows < cnt ----
#pragma unroll
    for (int t = 0; t < 2; t++) {
        int gr0 = mB + wm0 + t * 16 + r;
        int gr1 = gr0 + 8;
        bool k0 = gr0 < cnt;
        bool k1 = gr1 < cnt;
        if (!k0 && !k1) continue;
#pragma unroll
        for (int u = 0; u < 4; u++) {
            int col = nB + wn0 + u * 8 + c * 2;
            float v00 = acc[t][u][0], v01 = acc[t][u][1];
            float v10 = acc[t][u][2], v11 = acc[t][u][3];
            if (doGelu) {
                float b0v = bias[a * CR + col], b1v = bias[a * CR + col + 1];
                v00 = to_tf32(gelu_exact(v00 + b0v));
                v01 = to_tf32(gelu_exact(v01 + b1v));
                v10 = to_tf32(gelu_exact(v10 + b0v));
                v11 = to_tf32(gelu_exact(v11 + b1v));
            }
            if (k0) *(float2*)(C + (long)gr0 * ldc + col) = make_float2(v00, v01);
            if (k1) *(float2*)(C + (long)gr1 * ldc + col) = make_float2(v10, v11);
        }
    }
}

// ---------------- gather + mean + residual (NCHW) ----------------
__global__ void gather_kernel(const float* __restrict__ feat,
                              const float* __restrict__ ar,
                              float* __restrict__ out)
{
    int b  = blockIdx.z;
    int c0 = blockIdx.y * 32;
    int p0 = blockIdx.x * 32;
    int tx = threadIdx.x, ty = threadIdx.y;
    __shared__ float acc[32][33];
#pragma unroll
    for (int jj = 0; jj < 4; jj++) {
        int pi = ty + jj * 8;
        int p = p0 + pi;
        long tok = (long)b * HWSZ + p;
        float s = 0.f;
#pragma unroll
        for (int na = 0; na < NANCH; na++) {
            float v = ar[(long)(b * NANCH + na) * HWSZ + p];
            int a = adapter_idx(v);
            int slot = g_slot[a * NTOK + tok];
            s += g_outall[((long)a * NTOK + slot) * CDIM + c0 + tx];
        }
        acc[pi][tx] = s * (1.0f / 3.0f);
    }
    __syncthreads();
    int tid = ty * 32 + tx;
    int pi  = tid & 31;
    int ci0 = tid >> 5;
#pragma unroll
    for (int cj = 0; cj < 4; cj++) {
        int ci = ci0 + cj * 8;
        long off = (long)(b * CDIM + c0 + ci) * HWSZ + p0 + pi;
        out[off] = acc[pi][ci] + feat[off];
    }
}

// ---------------- launch ----------------
extern "C" void kernel_launch(void* const* d_in, const int* in_sizes, int n_in,
                              void* d_out, int out_size) {
    const float* feat     = (const float*)d_in[0];
    const float* ar       = (const float*)d_in[1];
    const float* ln_scale = (const float*)d_in[2];
    const float* ln_bias  = (const float*)d_in[3];
    const float* w1       = (const float*)d_in[4];
    const float* w2       = (const float*)d_in[5];
    float* out = (float*)d_out;

    float *norm, *w1t, *w2t, *bias1, *h, *outall;
    int *toklist;
    cudaGetSymbolAddress((void**)&norm,    g_norm);
    cudaGetSymbolAddress((void**)&w1t,     g_w1t);
    cudaGetSymbolAddress((void**)&w2t,     g_w2t);
    cudaGetSymbolAddress((void**)&bias1,   g_bias1);
    cudaGetSymbolAddress((void**)&h,       g_h);
    cudaGetSymbolAddress((void**)&outall,  g_outall);
    cudaGetSymbolAddress((void**)&toklist, g_toklist);

    static bool attr_set = false;
    if (!attr_set) {
        cudaFuncSetAttribute(mma_gemm, cudaFuncAttributeMaxDynamicSharedMemorySize, 65536);
        attr_set = true;
    }

    zero_cnt_kernel<<<1, 32>>>();
    compact_kernel<<<NTOK / 256, 256>>>(ar);
    prep_w1_kernel<<<dim3(CDIM / 32, CR / 32, NADP), dim3(32, 8)>>>(ln_scale, w1);
    prep_w2_kernel<<<dim3(CDIM / 32, CR / 32, NADP), dim3(32, 8)>>>(w2);
    fold_bias_part<<<dim3(NADP, 32), 256>>>(ln_bias, w1);
    fold_bias_reduce<<<(NADP * CR + 255) / 256, 256>>>();
    ln_stats_kernel<<<dim3(HWSZ / 32, BBAT), dim3(32, 8)>>>(feat);
    ln_apply_kernel<<<dim3(HWSZ / 32, CDIM / 32, BBAT), dim3(32, 8)>>>(feat);

    // GEMM1: h[a][slot] = gelu(norm[tok(slot)] @ w1t[a]^T + bias1[a])  N=256 K=1024
    mma_gemm<<<dim3(NTOK / 128, CR / 128, NADP), 512, 65536>>>(
        norm, w1t, bias1, h, toklist,
        CDIM, CDIM, CDIM, CR,
        0L, (long)CR * CDIM, (long)NTOK * CR, 1);

    // GEMM2: outall[a][slot] = h[a][slot] @ w2t[a]^T  N=1024 K=256
    mma_gemm<<<dim3(NTOK / 128, CDIM / 128, NADP), 512, 65536>>>(
        h, w2t, nullptr, outall, nullptr,
        CR, CR, CR, CDIM,
        (long)NTOK * CR, (long)CDIM * CR, (long)NTOK * CDIM, 0);

    gather_kernel<<<dim3(HWSZ / 32, CDIM / 32, BBAT), dim3(32, 8)>>>(feat, ar, out);
}

// round 9
// speedup vs baseline: 1.4743x; 1.3628x over previous
#include <cuda_runtime.h>
#include <cstdint>
#include <math.h>

#define NTOK 8192
#define CDIM 1024
#define CR   256
#define NADP 10
#define HWSZ 4096
#define BBAT 2
#define NANCH 3

// ---------------- scratch ----------------
static __device__ float g_norm[(long)NTOK * CDIM];
static __device__ float g_w1t[(long)NADP * CR * CDIM];
static __device__ float g_w2t[(long)NADP * CDIM * CR];
static __device__ float g_bias1[NADP * CR];
static __device__ float g_bpart[32][NADP * CR];
static __device__ float g_h[(long)NADP * NTOK * CR];
static __device__ float g_outall[(long)NADP * NTOK * CDIM];
static __device__ int   g_cnt[NADP];
static __device__ int   g_toklist[NADP * NTOK];
static __device__ int   g_slot[NADP * NTOK];
static __device__ float g_mean[NTOK];
static __device__ float g_rstd[NTOK];

// ---------------- helpers ----------------
__device__ __forceinline__ float to_tf32(float x) {
    uint32_t o; asm("cvt.rna.tf32.f32 %0, %1;" : "=r"(o) : "f"(x));
    return __uint_as_float(o);
}
__device__ __forceinline__ void mma_tf32(float* d, uint32_t a0, uint32_t a1, uint32_t a2, uint32_t a3,
                                         uint32_t b0, uint32_t b1) {
    asm volatile("mma.sync.aligned.m16n8k8.row.col.f32.tf32.tf32.f32 "
        "{%0,%1,%2,%3}, {%4,%5,%6,%7}, {%8,%9}, {%0,%1,%2,%3};"
        : "+f"(d[0]), "+f"(d[1]), "+f"(d[2]), "+f"(d[3])
        : "r"(a0), "r"(a1), "r"(a2), "r"(a3), "r"(b0), "r"(b1));
}
__device__ __forceinline__ void cp16(uint32_t dst, const void* src) {
    asm volatile("cp.async.cg.shared.global [%0], [%1], 16;" :: "r"(dst), "l"(src));
}
#define CP_COMMIT() asm volatile("cp.async.commit_group;" ::: "memory")
#define CP_WAIT(n)  asm volatile("cp.async.wait_group %0;" :: "n"(n) : "memory")
__device__ __forceinline__ uint32_t smem_u32(const void* p) {
    uint32_t a;
    asm("{ .reg .u64 t; cvta.to.shared.u64 t, %1; cvt.u32.u64 %0, t; }" : "=r"(a) : "l"(p));
    return a;
}
__device__ __forceinline__ float gelu_exact(float x) {
    return 0.5f * x * (1.0f + erff(x * 0.70710678118654752440f));
}
__device__ __forceinline__ int adapter_idx(float v) {
    int idx = 0;
    idx += v > (1.0f / 9.0f);
    idx += v > (1.0f / 7.0f);
    idx += v > (1.0f / 5.0f);
    idx += v > (1.0f / 3.0f);
    idx += v > 1.0f;
    idx += v > 3.0f;
    idx += v > 5.0f;
    idx += v > 7.0f;
    idx += v > 9.0f;
    return idx;
}

// ---------------- compaction ----------------
__global__ void zero_cnt_kernel() {
    if (threadIdx.x < NADP) g_cnt[threadIdx.x] = 0;
}
__global__ void compact_kernel(const float* __restrict__ ar) {
    int tok = blockIdx.x * 256 + threadIdx.x;
    if (tok >= NTOK) return;
    int b = tok >> 12, p = tok & (HWSZ - 1);
    int ids[NANCH];
#pragma unroll
    for (int na = 0; na < NANCH; na++)
        ids[na] = adapter_idx(ar[(long)(b * NANCH + na) * HWSZ + p]);
#pragma unroll
    for (int na = 0; na < NANCH; na++) {
        bool dup = false;
#pragma unroll
        for (int j = 0; j < NANCH; j++) if (j < na) dup |= (ids[j] == ids[na]);
        if (!dup) {
            int a = ids[na];
            int s = atomicAdd(&g_cnt[a], 1);
            g_toklist[a * NTOK + s] = tok;
            g_slot[a * NTOK + tok] = s;
        }
    }
}

// ---------------- weight prep ----------------
__global__ void prep_w1_kernel(const float* __restrict__ ln_scale, const float* __restrict__ w1) {
    __shared__ float t[32][33];
    int a = blockIdx.z, c0 = blockIdx.x * 32, d0 = blockIdx.y * 32;
    int tx = threadIdx.x, ty = threadIdx.y;
#pragma unroll
    for (int jj = 0; jj < 4; jj++) {
        int ci = ty + jj * 8;
        t[ci][tx] = w1[((long)a * CDIM + c0 + ci) * CR + d0 + tx] * ln_scale[a * CDIM + c0 + ci];
    }
    __syncthreads();
#pragma unroll
    for (int jj = 0; jj < 4; jj++) {
        int di = ty + jj * 8;
        g_w1t[((long)a * CR + d0 + di) * CDIM + c0 + tx] = to_tf32(t[tx][di]);
    }
}
__global__ void prep_w2_kernel(const float* __restrict__ w2) {
    __shared__ float t[32][33];
    int a = blockIdx.z, n0 = blockIdx.x * 32, k0 = blockIdx.y * 32;
    int tx = threadIdx.x, ty = threadIdx.y;
#pragma unroll
    for (int jj = 0; jj < 4; jj++) {
        int ki = ty + jj * 8;
        t[ki][tx] = w2[((long)a * CR + k0 + ki) * CDIM + n0 + tx];
    }
    __syncthreads();
#pragma unroll
    for (int jj = 0; jj < 4; jj++) {
        int ni = ty + jj * 8;
        g_w2t[((long)a * CDIM + n0 + ni) * CR + k0 + tx] = to_tf32(t[tx][ni]);
    }
}
__global__ void fold_bias_part(const float* __restrict__ ln_bias, const float* __restrict__ w1) {
    int a = blockIdx.x, ch = blockIdx.y, d = threadIdx.x;
    const float* wb = w1 + (long)a * CDIM * CR + (long)ch * 32 * CR;
    const float* lb = ln_bias + a * CDIM + ch * 32;
    float s = 0.f;
#pragma unroll
    for (int c = 0; c < 32; c++) s = fmaf(lb[c], wb[(long)c * CR + d], s);
    g_bpart[ch][a * CR + d] = s;
}
__global__ void fold_bias_reduce() {
    int i = blockIdx.x * 256 + threadIdx.x;
    if (i >= NADP * CR) return;
    float s = 0.f;
#pragma unroll
    for (int ch = 0; ch < 32; ch++) s += g_bpart[ch][i];
    g_bias1[i] = s;
}

// ---------------- LayerNorm ----------------
__global__ void ln_stats_kernel(const float* __restrict__ feat) {
    int b  = blockIdx.y;
    int p0 = blockIdx.x * 32;
    int tx = threadIdx.x, ty = threadIdx.y;
    const float* base = feat + (long)b * CDIM * HWSZ + p0 + tx;
    float s = 0.f, sq = 0.f;
#pragma unroll 16
    for (int c = ty; c < CDIM; c += 8) {
        float v = base[(long)c * HWSZ];
        s += v; sq = fmaf(v, v, sq);
    }
    __shared__ float ss[8][33], qq[8][33];
    ss[ty][tx] = s; qq[ty][tx] = sq;
    __syncthreads();
    if (ty == 0) {
        float S = 0.f, Q = 0.f;
#pragma unroll
        for (int j = 0; j < 8; j++) { S += ss[j][tx]; Q += qq[j][tx]; }
        float mean = S * (1.0f / CDIM);
        float var  = Q * (1.0f / CDIM) - mean * mean;
        int tok = b * HWSZ + p0 + tx;
        g_mean[tok] = mean;
        g_rstd[tok] = rsqrtf(var + 1e-5f);
    }
}
__global__ void ln_apply_kernel(const float* __restrict__ feat) {
    __shared__ float t[32][33];
    int b  = blockIdx.z;
    int c0 = blockIdx.y * 32;
    int p0 = blockIdx.x * 32;
    int tx = threadIdx.x, ty = threadIdx.y;
#pragma unroll
    for (int cj = 0; cj < 4; cj++) {
        int ci = ty + cj * 8;
        t[ci][tx] = feat[((long)b * CDIM + c0 + ci) * HWSZ + p0 + tx];
    }
    __syncthreads();
#pragma unroll
    for (int pj = 0; pj < 4; pj++) {
        int pi = ty + pj * 8;
        int tok = b * HWSZ + p0 + pi;
        float mean = g_mean[tok], rstd = g_rstd[tok];
        g_norm[(long)tok * CDIM + c0 + tx] = to_tf32((t[tx][pi] - mean) * rstd);
    }
}

// ---------------- tf32 mma.sync GEMM: 128x128 CTA, 4 warps of 64x64, cp.async 3-stage ----------------
// SMEM layout per stage (32KB): A tile [128 rows][32 k] then B tile, row-major with
// 16B-chunk XOR swizzle: word(row,k) = row*32 + (((k>>2) ^ (row&7))<<2) + (k&3).
#define G_STAGES   3
#define G_STAGE_B  32768
#define G_PTRS_B   2048
#define G_SMEM_TOTAL (G_PTRS_B + G_STAGES * G_STAGE_B)

__global__ void __launch_bounds__(128, 2)
mma_gemm(const float* __restrict__ Ab, const float* __restrict__ Bb,
         const float* __restrict__ bias, float* __restrict__ Cb,
         const int* __restrict__ toklist,
         int K, int lda, int ldb, int ldc,
         long sA, long sB, long sC, int doGelu)
{
    extern __shared__ char smem[];
    int tid = threadIdx.x;
    int mB = blockIdx.x * 128, nB = blockIdx.y * 128, a = blockIdx.z;

    int cnt = g_cnt[a];
    if (mB >= cnt) return;

    const float* A = Ab + (long)a * sA;
    const float* B = Bb + (long)a * sB;
    float* C = Cb + (long)a * sC;
    const int* tl = toklist ? toklist + a * NTOK : nullptr;

    const float** sAp = (const float**)smem;          // 128 ptrs
    const float** sBp = sAp + 128;                    // 128 ptrs
    uint32_t sm_base = smem_u32(smem) + G_PTRS_B;

    // row pointer tables
    {
        int m = mB + tid;
        int mc = m < cnt ? m : (cnt - 1);
        long arow = tl ? (long)tl[mc] : (long)mc;
        sAp[tid] = A + arow * lda;
        sBp[tid] = B + (long)(nB + tid) * ldb;
    }
    __syncthreads();

    int lane = tid & 31, wid = tid >> 5;
    int wm0 = (wid & 1) * 64;
    int wn0 = (wid >> 1) * 64;
    int r = lane >> 2, c = lane & 3;

    int nkt = K >> 5;
    int kc = tid & 7;      // 16B chunk within row
    int r0 = tid >> 3;     // base row for fills

    // fill one stage: A tile + B tile, 8 rows apart per thread
#define FILL_STAGE(sidx, k0)  do {                                          \
        uint32_t base = sm_base + (sidx) * G_STAGE_B;                       \
        _Pragma("unroll")                                                   \
        for (int i = 0; i < 8; i++) {                                       \
            int row = r0 + i * 16;                                          \
            uint32_t off = (uint32_t)(row * 32 + ((kc ^ (row & 7)) << 2)) * 4; \
            cp16(base + off, sAp[row] + (k0) + kc * 4);                     \
            cp16(base + 16384 + off, sBp[row] + (k0) + kc * 4);             \
        }                                                                   \
        CP_COMMIT();                                                        \
    } while (0)

    float acc[4][8][4];
#pragma unroll
    for (int t = 0; t < 4; t++)
#pragma unroll
        for (int u = 0; u < 8; u++)
#pragma unroll
            for (int e = 0; e < 4; e++) acc[t][u][e] = 0.f;

    // prologue: stages 0,1
    FILL_STAGE(0, 0);
    FILL_STAGE(1, 32);
    CP_WAIT(1);
    __syncthreads();

    for (int kt = 0; kt < nkt; kt++) {
        const float* As = (const float*)(smem + G_PTRS_B + (kt % 3) * G_STAGE_B);
        const float* Bs = As + 4096;

#pragma unroll
        for (int j = 0; j < 4; j++) {
            // B frags: b0 = B^T[n][c+8j], b1 = B^T[n][c+4+8j]
            float bf[8][2];
#pragma unroll
            for (int u = 0; u < 8; u++) {
                int n = wn0 + u * 8 + r;
                int nb = n * 32;
                int sw = (n & 7);
                bf[u][0] = Bs[nb + (((2 * j)     ^ sw) << 2) + c];
                bf[u][1] = Bs[nb + (((2 * j + 1) ^ sw) << 2) + c];
            }
#pragma unroll
            for (int t = 0; t < 4; t++) {
                int m0 = wm0 + t * 16 + r;
                int sw = (m0 & 7);
                int rb0 = m0 * 32;
                int rb1 = (m0 + 8) * 32;
                float a0 = As[rb0 + (((2 * j)     ^ sw) << 2) + c];
                float a1 = As[rb1 + (((2 * j)     ^ sw) << 2) + c];
                float a2 = As[rb0 + (((2 * j + 1) ^ sw) << 2) + c];
                float a3 = As[rb1 + (((2 * j + 1) ^ sw) << 2) + c];
#pragma unroll
                for (int u = 0; u < 8; u++)
                    mma_tf32(acc[t][u],
                             __float_as_uint(a0), __float_as_uint(a1),
                             __float_as_uint(a2), __float_as_uint(a3),
                             __float_as_uint(bf[u][0]), __float_as_uint(bf[u][1]));
            }
        }

        if (kt + 2 < nkt) {
            __syncthreads();                 // stage (kt+2)%3 free to overwrite
            FILL_STAGE((kt + 2) % 3, (kt + 2) * 32);
            CP_WAIT(1);                      // stage kt+1 complete
            __syncthreads();
        } else if (kt + 1 < nkt) {
            CP_WAIT(0);
            __syncthreads();
        }
    }

    // ---- epilogue ----
#pragma unroll
    for (int t = 0; t < 4; t++) {
        int gr0 = mB + wm0 + t * 16 + r;
        int gr1 = gr0 + 8;
        bool k0 = gr0 < cnt;
        bool k1 = gr1 < cnt;
        if (!k0 && !k1) continue;
#pragma unroll
        for (int u = 0; u < 8; u++) {
            int col = nB + wn0 + u * 8 + c * 2;
            float v00 = acc[t][u][0], v01 = acc[t][u][1];
            float v10 = acc[t][u][2], v11 = acc[t][u][3];
            if (doGelu) {
                float b0v = bias[a * CR + col], b1v = bias[a * CR + col + 1];
                v00 = to_tf32(gelu_exact(v00 + b0v));
                v01 = to_tf32(gelu_exact(v01 + b1v));
                v10 = to_tf32(gelu_exact(v10 + b0v));
                v11 = to_tf32(gelu_exact(v11 + b1v));
            }
            if (k0) *(float2*)(C + (long)gr0 * ldc + col) = make_float2(v00, v01);
            if (k1) *(float2*)(C + (long)gr1 * ldc + col) = make_float2(v10, v11);
        }
    }
#undef FILL_STAGE
}

// ---------------- gather + mean + residual (NCHW) ----------------
__global__ void gather_kernel(const float* __restrict__ feat,
                              const float* __restrict__ ar,
                              float* __restrict__ out)
{
    int b  = blockIdx.z;
    int c0 = blockIdx.y * 32;
    int p0 = blockIdx.x * 32;
    int tx = threadIdx.x, ty = threadIdx.y;
    __shared__ float acc[32][33];
#pragma unroll
    for (int jj = 0; jj < 4; jj++) {
        int pi = ty + jj * 8;
        int p = p0 + pi;
        long tok = (long)b * HWSZ + p;
        float s = 0.f;
#pragma unroll
        for (int na = 0; na < NANCH; na++) {
            float v = ar[(long)(b * NANCH + na) * HWSZ + p];
            int a = adapter_idx(v);
            int slot = g_slot[a * NTOK + tok];
            s += g_outall[((long)a * NTOK + slot) * CDIM + c0 + tx];
        }
        acc[pi][tx] = s * (1.0f / 3.0f);
    }
    __syncthreads();
    int tid = ty * 32 + tx;
    int pi  = tid & 31;
    int ci0 = tid >> 5;
#pragma unroll
    for (int cj = 0; cj < 4; cj++) {
        int ci = ci0 + cj * 8;
        long off = (long)(b * CDIM + c0 + ci) * HWSZ + p0 + pi;
        out[off] = acc[pi][ci] + feat[off];
    }
}

// ---------------- launch ----------------
extern "C" void kernel_launch(void* const* d_in, const int* in_sizes, int n_in,
                              void* d_out, int out_size) {
    const float* feat     = (const float*)d_in[0];
    const float* ar       = (const float*)d_in[1];
    const float* ln_scale = (const float*)d_in[2];
    const float* ln_bias  = (const float*)d_in[3];
    const float* w1       = (const float*)d_in[4];
    const float* w2       = (const float*)d_in[5];
    float* out = (float*)d_out;

    float *norm, *w1t, *w2t, *bias1, *h, *outall;
    int *toklist;
    cudaGetSymbolAddress((void**)&norm,    g_norm);
    cudaGetSymbolAddress((void**)&w1t,     g_w1t);
    cudaGetSymbolAddress((void**)&w2t,     g_w2t);
    cudaGetSymbolAddress((void**)&bias1,   g_bias1);
    cudaGetSymbolAddress((void**)&h,       g_h);
    cudaGetSymbolAddress((void**)&outall,  g_outall);
    cudaGetSymbolAddress((void**)&toklist, g_toklist);

    static bool attr_set = false;
    if (!attr_set) {
        cudaFuncSetAttribute(mma_gemm, cudaFuncAttributeMaxDynamicSharedMemorySize, G_SMEM_TOTAL);
        attr_set = true;
    }

    zero_cnt_kernel<<<1, 32>>>();
    compact_kernel<<<NTOK / 256, 256>>>(ar);
    prep_w1_kernel<<<dim3(CDIM / 32, CR / 32, NADP), dim3(32, 8)>>>(ln_scale, w1);
    prep_w2_kernel<<<dim3(CDIM / 32, CR / 32, NADP), dim3(32, 8)>>>(w2);
    fold_bias_part<<<dim3(NADP, 32), 256>>>(ln_bias, w1);
    fold_bias_reduce<<<(NADP * CR + 255) / 256, 256>>>();
    ln_stats_kernel<<<dim3(HWSZ / 32, BBAT), dim3(32, 8)>>>(feat);
    ln_apply_kernel<<<dim3(HWSZ / 32, CDIM / 32, BBAT), dim3(32, 8)>>>(feat);

    // GEMM1: h[a][slot] = gelu(norm[tok(slot)] @ w1t[a]^T + bias1[a])  N=256 K=1024
    mma_gemm<<<dim3(NTOK / 128, CR / 128, NADP), 128, G_SMEM_TOTAL>>>(
        norm, w1t, bias1, h, toklist,
        CDIM, CDIM, CDIM, CR,
        0L, (long)CR * CDIM, (long)NTOK * CR, 1);

    // GEMM2: outall[a][slot] = h[a][slot] @ w2t[a]^T  N=1024 K=256
    mma_gemm<<<dim3(NTOK / 128, CDIM / 128, NADP), 128, G_SMEM_TOTAL>>>(
        h, w2t, nullptr, outall, nullptr,
        CR, CR, CR, CDIM,
        (long)NTOK * CR, (long)CDIM * CR, (long)NTOK * CDIM, 0);

    gather_kernel<<<dim3(HWSZ / 32, CDIM / 32, BBAT), dim3(32, 8)>>>(feat, ar, out);
}

// round 10
// speedup vs baseline: 1.5949x; 1.0819x over previous
#include <cuda_runtime.h>
#include <cstdint>
#include <math.h>

#define NTOK 8192
#define CDIM 1024
#define CR   256
#define NADP 10
#define HWSZ 4096
#define BBAT 2
#define NANCH 3

// ---------------- scratch ----------------
static __device__ float g_norm[(long)NTOK * CDIM];
static __device__ float g_w1t[(long)NADP * CR * CDIM];
static __device__ float g_w2t[(long)NADP * CDIM * CR];
static __device__ float g_bias1[NADP * CR];
static __device__ float g_bpart[32][NADP * CR];
static __device__ float g_h[(long)NADP * NTOK * CR];
static __device__ float g_accum[(long)NTOK * CDIM];   // fused gather accumulator
static __device__ int   g_cnt[NADP];
static __device__ int   g_toklist[NADP * NTOK];
static __device__ float g_wt[NADP * NTOK];            // weight per (a, slot) = count/3
static __device__ float g_mean[NTOK];
static __device__ float g_rstd[NTOK];

// ---------------- helpers ----------------
__device__ __forceinline__ float to_tf32(float x) {
    uint32_t o; asm("cvt.rna.tf32.f32 %0, %1;" : "=r"(o) : "f"(x));
    return __uint_as_float(o);
}
__device__ __forceinline__ void mma_tf32(float* d, uint32_t a0, uint32_t a1, uint32_t a2, uint32_t a3,
                                         uint32_t b0, uint32_t b1) {
    asm volatile("mma.sync.aligned.m16n8k8.row.col.f32.tf32.tf32.f32 "
        "{%0,%1,%2,%3}, {%4,%5,%6,%7}, {%8,%9}, {%0,%1,%2,%3};"
        : "+f"(d[0]), "+f"(d[1]), "+f"(d[2]), "+f"(d[3])
        : "r"(a0), "r"(a1), "r"(a2), "r"(a3), "r"(b0), "r"(b1));
}
__device__ __forceinline__ void cp16(uint32_t dst, const void* src) {
    asm volatile("cp.async.cg.shared.global [%0], [%1], 16;" :: "r"(dst), "l"(src));
}
#define CP_COMMIT() asm volatile("cp.async.commit_group;" ::: "memory")
#define CP_WAIT(n)  asm volatile("cp.async.wait_group %0;" :: "n"(n) : "memory")
__device__ __forceinline__ uint32_t smem_u32(const void* p) {
    uint32_t a;
    asm("{ .reg .u64 t; cvta.to.shared.u64 t, %1; cvt.u32.u64 %0, t; }" : "=r"(a) : "l"(p));
    return a;
}
__device__ __forceinline__ float gelu_exact(float x) {
    return 0.5f * x * (1.0f + erff(x * 0.70710678118654752440f));
}
__device__ __forceinline__ int adapter_idx(float v) {
    int idx = 0;
    idx += v > (1.0f / 9.0f);
    idx += v > (1.0f / 7.0f);
    idx += v > (1.0f / 5.0f);
    idx += v > (1.0f / 3.0f);
    idx += v > 1.0f;
    idx += v > 3.0f;
    idx += v > 5.0f;
    idx += v > 7.0f;
    idx += v > 9.0f;
    return idx;
}

// ---------------- compaction (+ per-slot weights) ----------------
__global__ void zero_cnt_kernel() {
    if (threadIdx.x < NADP) g_cnt[threadIdx.x] = 0;
}
__global__ void compact_kernel(const float* __restrict__ ar) {
    int tok = blockIdx.x * 256 + threadIdx.x;
    if (tok >= NTOK) return;
    int b = tok >> 12, p = tok & (HWSZ - 1);
    int ids[NANCH];
#pragma unroll
    for (int na = 0; na < NANCH; na++)
        ids[na] = adapter_idx(ar[(long)(b * NANCH + na) * HWSZ + p]);
#pragma unroll
    for (int na = 0; na < NANCH; na++) {
        bool dup = false;
#pragma unroll
        for (int j = 0; j < NANCH; j++) if (j < na) dup |= (ids[j] == ids[na]);
        if (!dup) {
            int occ = 0;
#pragma unroll
            for (int j = 0; j < NANCH; j++) occ += (ids[j] == ids[na]);
            int a = ids[na];
            int s = atomicAdd(&g_cnt[a], 1);
            g_toklist[a * NTOK + s] = tok;
            g_wt[a * NTOK + s] = (float)occ * (1.0f / 3.0f);
        }
    }
}

// ---------------- weight prep ----------------
__global__ void prep_w1_kernel(const float* __restrict__ ln_scale, const float* __restrict__ w1) {
    __shared__ float t[32][33];
    int a = blockIdx.z, c0 = blockIdx.x * 32, d0 = blockIdx.y * 32;
    int tx = threadIdx.x, ty = threadIdx.y;
#pragma unroll
    for (int jj = 0; jj < 4; jj++) {
        int ci = ty + jj * 8;
        t[ci][tx] = w1[((long)a * CDIM + c0 + ci) * CR + d0 + tx] * ln_scale[a * CDIM + c0 + ci];
    }
    __syncthreads();
#pragma unroll
    for (int jj = 0; jj < 4; jj++) {
        int di = ty + jj * 8;
        g_w1t[((long)a * CR + d0 + di) * CDIM + c0 + tx] = to_tf32(t[tx][di]);
    }
}
__global__ void prep_w2_kernel(const float* __restrict__ w2) {
    __shared__ float t[32][33];
    int a = blockIdx.z, n0 = blockIdx.x * 32, k0 = blockIdx.y * 32;
    int tx = threadIdx.x, ty = threadIdx.y;
#pragma unroll
    for (int jj = 0; jj < 4; jj++) {
        int ki = ty + jj * 8;
        t[ki][tx] = w2[((long)a * CR + k0 + ki) * CDIM + n0 + tx];
    }
    __syncthreads();
#pragma unroll
    for (int jj = 0; jj < 4; jj++) {
        int ni = ty + jj * 8;
        g_w2t[((long)a * CDIM + n0 + ni) * CR + k0 + tx] = to_tf32(t[tx][ni]);
    }
}
__global__ void fold_bias_part(const float* __restrict__ ln_bias, const float* __restrict__ w1) {
    int a = blockIdx.x, ch = blockIdx.y, d = threadIdx.x;
    const float* wb = w1 + (long)a * CDIM * CR + (long)ch * 32 * CR;
    const float* lb = ln_bias + a * CDIM + ch * 32;
    float s = 0.f;
#pragma unroll
    for (int c = 0; c < 32; c++) s = fmaf(lb[c], wb[(long)c * CR + d], s);
    g_bpart[ch][a * CR + d] = s;
}
__global__ void fold_bias_reduce() {
    int i = blockIdx.x * 256 + threadIdx.x;
    if (i >= NADP * CR) return;
    float s = 0.f;
#pragma unroll
    for (int ch = 0; ch < 32; ch++) s += g_bpart[ch][i];
    g_bias1[i] = s;
}

// ---------------- LayerNorm ----------------
__global__ void ln_stats_kernel(const float* __restrict__ feat) {
    int b  = blockIdx.y;
    int p0 = blockIdx.x * 32;
    int tx = threadIdx.x, ty = threadIdx.y;
    const float* base = feat + (long)b * CDIM * HWSZ + p0 + tx;
    float s = 0.f, sq = 0.f;
#pragma unroll 16
    for (int c = ty; c < CDIM; c += 8) {
        float v = base[(long)c * HWSZ];
        s += v; sq = fmaf(v, v, sq);
    }
    __shared__ float ss[8][33], qq[8][33];
    ss[ty][tx] = s; qq[ty][tx] = sq;
    __syncthreads();
    if (ty == 0) {
        float S = 0.f, Q = 0.f;
#pragma unroll
        for (int j = 0; j < 8; j++) { S += ss[j][tx]; Q += qq[j][tx]; }
        float mean = S * (1.0f / CDIM);
        float var  = Q * (1.0f / CDIM) - mean * mean;
        int tok = b * HWSZ + p0 + tx;
        g_mean[tok] = mean;
        g_rstd[tok] = rsqrtf(var + 1e-5f);
    }
}
__global__ void ln_apply_kernel(const float* __restrict__ feat) {
    __shared__ float t[32][33];
    int b  = blockIdx.z;
    int c0 = blockIdx.y * 32;
    int p0 = blockIdx.x * 32;
    int tx = threadIdx.x, ty = threadIdx.y;
#pragma unroll
    for (int cj = 0; cj < 4; cj++) {
        int ci = ty + cj * 8;
        t[ci][tx] = feat[((long)b * CDIM + c0 + ci) * HWSZ + p0 + tx];
    }
    __syncthreads();
#pragma unroll
    for (int pj = 0; pj < 4; pj++) {
        int pi = ty + pj * 8;
        int tok = b * HWSZ + p0 + pi;
        float mean = g_mean[tok], rstd = g_rstd[tok];
        g_norm[(long)tok * CDIM + c0 + tx] = to_tf32((t[tx][pi] - mean) * rstd);
    }
}

// ---------------- tf32 mma.sync GEMM: 128x128 CTA, 4 warps of 64x64, cp.async 3-stage ----------------
#define G_STAGES   3
#define G_STAGE_B  32768
#define G_PTRS_B   2048
#define G_SMEM_TOTAL (G_PTRS_B + G_STAGES * G_STAGE_B)

// mode 0: plain store. mode 1: gelu(x+bias) store. mode 2: weighted atomic accum into accumC[tok][*].
__global__ void __launch_bounds__(128, 2)
mma_gemm(const float* __restrict__ Ab, const float* __restrict__ Bb,
         const float* __restrict__ bias, float* __restrict__ Cb,
         const int* __restrict__ tlA,      // gather list for A rows (or null)
         const int* __restrict__ tlE,      // slot->tok map for accum epilogue (or null)
         const float* __restrict__ wts,    // per-slot weight (mode 2)
         float* __restrict__ accumC,       // accum buffer (mode 2)
         int K, int lda, int ldb, int ldc,
         long sA, long sB, long sC, int mode)
{
    extern __shared__ char smem[];
    int tid = threadIdx.x;
    int mB = blockIdx.x * 128, nB = blockIdx.y * 128, a = blockIdx.z;

    int cnt = g_cnt[a];
    if (mB >= cnt) return;

    const float* A = Ab + (long)a * sA;
    const float* B = Bb + (long)a * sB;
    float* C = Cb + (long)a * sC;
    const int* tla = tlA ? tlA + a * NTOK : nullptr;

    const float** sAp = (const float**)smem;
    const float** sBp = sAp + 128;
    uint32_t sm_base = smem_u32(smem) + G_PTRS_B;

    {
        int m = mB + tid;
        int mc = m < cnt ? m : (cnt - 1);
        long arow = tla ? (long)tla[mc] : (long)mc;
        sAp[tid] = A + arow * lda;
        sBp[tid] = B + (long)(nB + tid) * ldb;
    }
    __syncthreads();

    int lane = tid & 31, wid = tid >> 5;
    int wm0 = (wid & 1) * 64;
    int wn0 = (wid >> 1) * 64;
    int r = lane >> 2, c = lane & 3;

    int nkt = K >> 5;
    int kc = tid & 7;
    int r0 = tid >> 3;

#define FILL_STAGE(sidx, k0)  do {                                          \
        uint32_t base = sm_base + (sidx) * G_STAGE_B;                       \
        _Pragma("unroll")                                                   \
        for (int i = 0; i < 8; i++) {                                       \
            int row = r0 + i * 16;                                          \
            uint32_t off = (uint32_t)(row * 32 + ((kc ^ (row & 7)) << 2)) * 4; \
            cp16(base + off, sAp[row] + (k0) + kc * 4);                     \
            cp16(base + 16384 + off, sBp[row] + (k0) + kc * 4);             \
        }                                                                   \
        CP_COMMIT();                                                        \
    } while (0)

    float acc[4][8][4];
#pragma unroll
    for (int t = 0; t < 4; t++)
#pragma unroll
        for (int u = 0; u < 8; u++)
#pragma unroll
            for (int e = 0; e < 4; e++) acc[t][u][e] = 0.f;

    FILL_STAGE(0, 0);
    FILL_STAGE(1, 32);
    CP_WAIT(1);
    __syncthreads();

    for (int kt = 0; kt < nkt; kt++) {
        const float* As = (const float*)(smem + G_PTRS_B + (kt % 3) * G_STAGE_B);
        const float* Bs = As + 4096;

#pragma unroll
        for (int j = 0; j < 4; j++) {
            float bf[8][2];
#pragma unroll
            for (int u = 0; u < 8; u++) {
                int n = wn0 + u * 8 + r;
                int nb = n * 32;
                int sw = (n & 7);
                bf[u][0] = Bs[nb + (((2 * j)     ^ sw) << 2) + c];
                bf[u][1] = Bs[nb + (((2 * j + 1) ^ sw) << 2) + c];
            }
#pragma unroll
            for (int t = 0; t < 4; t++) {
                int m0 = wm0 + t * 16 + r;
                int sw = (m0 & 7);
                int rb0 = m0 * 32;
                int rb1 = (m0 + 8) * 32;
                float a0 = As[rb0 + (((2 * j)     ^ sw) << 2) + c];
                float a1 = As[rb1 + (((2 * j)     ^ sw) << 2) + c];
                float a2 = As[rb0 + (((2 * j + 1) ^ sw) << 2) + c];
                float a3 = As[rb1 + (((2 * j + 1) ^ sw) << 2) + c];
#pragma unroll
                for (int u = 0; u < 8; u++)
                    mma_tf32(acc[t][u],
                             __float_as_uint(a0), __float_as_uint(a1),
                             __float_as_uint(a2), __float_as_uint(a3),
                             __float_as_uint(bf[u][0]), __float_as_uint(bf[u][1]));
            }
        }

        if (kt + 2 < nkt) {
            __syncthreads();
            FILL_STAGE((kt + 2) % 3, (kt + 2) * 32);
            CP_WAIT(1);
            __syncthreads();
        } else if (kt + 1 < nkt) {
            CP_WAIT(0);
            __syncthreads();
        }
    }

    // ---- epilogue ----
    if (mode == 2) {
        const int* tle = tlE + a * NTOK;
        const float* wta = wts + a * NTOK;
#pragma unroll
        for (int t = 0; t < 4; t++) {
            int gr0 = mB + wm0 + t * 16 + r;
            int gr1 = gr0 + 8;
            bool k0 = gr0 < cnt;
            bool k1 = gr1 < cnt;
            if (!k0 && !k1) continue;
            long t0 = k0 ? (long)tle[gr0] : 0;
            long t1 = k1 ? (long)tle[gr1] : 0;
            float w0 = k0 ? wta[gr0] : 0.f;
            float w1v = k1 ? wta[gr1] : 0.f;
            float* d0 = accumC + t0 * CDIM;
            float* d1 = accumC + t1 * CDIM;
#pragma unroll
            for (int u = 0; u < 8; u++) {
                int col = nB + wn0 + u * 8 + c * 2;
                if (k0) {
                    atomicAdd(d0 + col,     acc[t][u][0] * w0);
                    atomicAdd(d0 + col + 1, acc[t][u][1] * w0);
                }
                if (k1) {
                    atomicAdd(d1 + col,     acc[t][u][2] * w1v);
                    atomicAdd(d1 + col + 1, acc[t][u][3] * w1v);
                }
            }
        }
    } else {
#pragma unroll
        for (int t = 0; t < 4; t++) {
            int gr0 = mB + wm0 + t * 16 + r;
            int gr1 = gr0 + 8;
            bool k0 = gr0 < cnt;
            bool k1 = gr1 < cnt;
            if (!k0 && !k1) continue;
#pragma unroll
            for (int u = 0; u < 8; u++) {
                int col = nB + wn0 + u * 8 + c * 2;
                float v00 = acc[t][u][0], v01 = acc[t][u][1];
                float v10 = acc[t][u][2], v11 = acc[t][u][3];
                if (mode == 1) {
                    float b0v = bias[a * CR + col], b1v = bias[a * CR + col + 1];
                    v00 = to_tf32(gelu_exact(v00 + b0v));
                    v01 = to_tf32(gelu_exact(v01 + b1v));
                    v10 = to_tf32(gelu_exact(v10 + b0v));
                    v11 = to_tf32(gelu_exact(v11 + b1v));
                }
                if (k0) *(float2*)(C + (long)gr0 * ldc + col) = make_float2(v00, v01);
                if (k1) *(float2*)(C + (long)gr1 * ldc + col) = make_float2(v10, v11);
            }
        }
    }
#undef FILL_STAGE
}

// ---------------- final: out = accum (already /3-weighted) + feat, NCHW ----------------
__global__ void final_kernel(const float* __restrict__ feat, float* __restrict__ out) {
    __shared__ float t[32][33];
    int b  = blockIdx.z;
    int c0 = blockIdx.y * 32;
    int p0 = blockIdx.x * 32;
    int tx = threadIdx.x, ty = threadIdx.y;
#pragma unroll
    for (int pj = 0; pj < 4; pj++) {
        int pi = ty + pj * 8;
        long tok = (long)b * HWSZ + p0 + pi;
        t[pi][tx] = g_accum[tok * CDIM + c0 + tx];
    }
    __syncthreads();
    int tid = ty * 32 + tx;
    int pi  = tid & 31;
    int ci0 = tid >> 5;
#pragma unroll
    for (int cj = 0; cj < 4; cj++) {
        int ci = ci0 + cj * 8;
        long off = (long)(b * CDIM + c0 + ci) * HWSZ + p0 + pi;
        out[off] = t[pi][ci] + feat[off];
    }
}

// ---------------- launch ----------------
extern "C" void kernel_launch(void* const* d_in, const int* in_sizes, int n_in,
                              void* d_out, int out_size) {
    const float* feat     = (const float*)d_in[0];
    const float* ar       = (const float*)d_in[1];
    const float* ln_scale = (const float*)d_in[2];
    const float* ln_bias  = (const float*)d_in[3];
    const float* w1       = (const float*)d_in[4];
    const float* w2       = (const float*)d_in[5];
    float* out = (float*)d_out;

    float *norm, *w1t, *w2t, *bias1, *h, *accum, *wt;
    int *toklist;
    cudaGetSymbolAddress((void**)&norm,    g_norm);
    cudaGetSymbolAddress((void**)&w1t,     g_w1t);
    cudaGetSymbolAddress((void**)&w2t,     g_w2t);
    cudaGetSymbolAddress((void**)&bias1,   g_bias1);
    cudaGetSymbolAddress((void**)&h,       g_h);
    cudaGetSymbolAddress((void**)&accum,   g_accum);
    cudaGetSymbolAddress((void**)&toklist, g_toklist);
    cudaGetSymbolAddress((void**)&wt,      g_wt);

    static bool attr_set = false;
    if (!attr_set) {
        cudaFuncSetAttribute(mma_gemm, cudaFuncAttributeMaxDynamicSharedMemorySize, G_SMEM_TOTAL);
        attr_set = true;
    }

    cudaMemsetAsync(accum, 0, (long)NTOK * CDIM * sizeof(float));
    zero_cnt_kernel<<<1, 32>>>();
    compact_kernel<<<NTOK / 256, 256>>>(ar);
    prep_w1_kernel<<<dim3(CDIM / 32, CR / 32, NADP), dim3(32, 8)>>>(ln_scale, w1);
    prep_w2_kernel<<<dim3(CDIM / 32, CR / 32, NADP), dim3(32, 8)>>>(w2);
    fold_bias_part<<<dim3(NADP, 32), 256>>>(ln_bias, w1);
    fold_bias_reduce<<<(NADP * CR + 255) / 256, 256>>>();
    ln_stats_kernel<<<dim3(HWSZ / 32, BBAT), dim3(32, 8)>>>(feat);
    ln_apply_kernel<<<dim3(HWSZ / 32, CDIM / 32, BBAT), dim3(32, 8)>>>(feat);

    // GEMM1 (mode 1): h[a][slot] = gelu(norm[tok(slot)] @ w1t[a]^T + bias1[a])
    mma_gemm<<<dim3(NTOK / 128, CR / 128, NADP), 128, G_SMEM_TOTAL>>>(
        norm, w1t, bias1, h, toklist, nullptr, nullptr, nullptr,
        CDIM, CDIM, CDIM, CR,
        0L, (long)CR * CDIM, (long)NTOK * CR, 1);

    // GEMM2 (mode 2): accum[tok] += w * (h[a][slot] @ w2t[a]^T)
    mma_gemm<<<dim3(NTOK / 128, CDIM / 128, NADP), 128, G_SMEM_TOTAL>>>(
        h, w2t, nullptr, nullptr, nullptr, toklist, wt, accum,
        CR, CR, CR, CDIM,
        (long)NTOK * CR, (long)CDIM * CR, 0L, 2);

    // final: out = accum + feat (NCHW)
    final_kernel<<<dim3(HWSZ / 32, CDIM / 32, BBAT), dim3(32, 8)>>>(feat, out);
}

// round 11
// speedup vs baseline: 2.1622x; 1.3557x over previous
#include <cuda_runtime.h>
#include <cuda_fp16.h>
#include <cstdint>
#include <math.h>

#define NTOK 8192
#define CDIM 1024
#define CR   256
#define NADP 10
#define HWSZ 4096
#define BBAT 2
#define NANCH 3

// ---------------- scratch ----------------
static __device__ __half g_norm[(long)NTOK * CDIM];
static __device__ __half g_w1t[(long)NADP * CR * CDIM];
static __device__ __half g_w2t[(long)NADP * CDIM * CR];
static __device__ float  g_bias1[NADP * CR];
static __device__ float  g_bpart[32][NADP * CR];
static __device__ __half g_h[(long)NADP * NTOK * CR];
static __device__ float  g_accum[(long)NTOK * CDIM];
static __device__ int    g_cnt[NADP];
static __device__ int    g_toklist[NADP * NTOK];
static __device__ float  g_wt[NADP * NTOK];
static __device__ float  g_mean[NTOK];
static __device__ float  g_rstd[NTOK];

// ---------------- helpers ----------------
__device__ __forceinline__ void mma_f16(float* d, uint32_t a0, uint32_t a1, uint32_t a2, uint32_t a3,
                                        uint32_t b0, uint32_t b1) {
    asm volatile("mma.sync.aligned.m16n8k16.row.col.f32.f16.f16.f32 "
        "{%0,%1,%2,%3}, {%4,%5,%6,%7}, {%8,%9}, {%0,%1,%2,%3};"
        : "+f"(d[0]), "+f"(d[1]), "+f"(d[2]), "+f"(d[3])
        : "r"(a0), "r"(a1), "r"(a2), "r"(a3), "r"(b0), "r"(b1));
}
__device__ __forceinline__ void cp16(uint32_t dst, const void* src) {
    asm volatile("cp.async.cg.shared.global [%0], [%1], 16;" :: "r"(dst), "l"(src));
}
#define CP_COMMIT() asm volatile("cp.async.commit_group;" ::: "memory")
#define CP_WAIT(n)  asm volatile("cp.async.wait_group %0;" :: "n"(n) : "memory")
__device__ __forceinline__ uint32_t smem_u32(const void* p) {
    uint32_t a;
    asm("{ .reg .u64 t; cvta.to.shared.u64 t, %1; cvt.u32.u64 %0, t; }" : "=r"(a) : "l"(p));
    return a;
}
__device__ __forceinline__ float gelu_exact(float x) {
    return 0.5f * x * (1.0f + erff(x * 0.70710678118654752440f));
}
__device__ __forceinline__ int adapter_idx(float v) {
    int idx = 0;
    idx += v > (1.0f / 9.0f);
    idx += v > (1.0f / 7.0f);
    idx += v > (1.0f / 5.0f);
    idx += v > (1.0f / 3.0f);
    idx += v > 1.0f;
    idx += v > 3.0f;
    idx += v > 5.0f;
    idx += v > 7.0f;
    idx += v > 9.0f;
    return idx;
}
// swizzled byte offset within a 64B-row half tile: 4 chunks of 16B per row
__device__ __forceinline__ uint32_t lds_u32(const char* base, int row, int ch, int c) {
    return *(const uint32_t*)(base + row * 64 + ((ch ^ ((row >> 1) & 3)) << 4) + c * 4);
}

// ---------------- compaction (+ per-slot weights) ----------------
__global__ void zero_cnt_kernel() {
    if (threadIdx.x < NADP) g_cnt[threadIdx.x] = 0;
}
__global__ void compact_kernel(const float* __restrict__ ar) {
    int tok = blockIdx.x * 256 + threadIdx.x;
    if (tok >= NTOK) return;
    int b = tok >> 12, p = tok & (HWSZ - 1);
    int ids[NANCH];
#pragma unroll
    for (int na = 0; na < NANCH; na++)
        ids[na] = adapter_idx(ar[(long)(b * NANCH + na) * HWSZ + p]);
#pragma unroll
    for (int na = 0; na < NANCH; na++) {
        bool dup = false;
#pragma unroll
        for (int j = 0; j < NANCH; j++) if (j < na) dup |= (ids[j] == ids[na]);
        if (!dup) {
            int occ = 0;
#pragma unroll
            for (int j = 0; j < NANCH; j++) occ += (ids[j] == ids[na]);
            int a = ids[na];
            int s = atomicAdd(&g_cnt[a], 1);
            g_toklist[a * NTOK + s] = tok;
            g_wt[a * NTOK + s] = (float)occ * (1.0f / 3.0f);
        }
    }
}

// ---------------- weight prep ----------------
__global__ void prep_w1_kernel(const float* __restrict__ ln_scale, const float* __restrict__ w1) {
    __shared__ float t[32][33];
    int a = blockIdx.z, c0 = blockIdx.x * 32, d0 = blockIdx.y * 32;
    int tx = threadIdx.x, ty = threadIdx.y;
#pragma unroll
    for (int jj = 0; jj < 4; jj++) {
        int ci = ty + jj * 8;
        t[ci][tx] = w1[((long)a * CDIM + c0 + ci) * CR + d0 + tx] * ln_scale[a * CDIM + c0 + ci];
    }
    __syncthreads();
#pragma unroll
    for (int jj = 0; jj < 4; jj++) {
        int di = ty + jj * 8;
        g_w1t[((long)a * CR + d0 + di) * CDIM + c0 + tx] = __float2half_rn(t[tx][di]);
    }
}
__global__ void prep_w2_kernel(const float* __restrict__ w2) {
    __shared__ float t[32][33];
    int a = blockIdx.z, n0 = blockIdx.x * 32, k0 = blockIdx.y * 32;
    int tx = threadIdx.x, ty = threadIdx.y;
#pragma unroll
    for (int jj = 0; jj < 4; jj++) {
        int ki = ty + jj * 8;
        t[ki][tx] = w2[((long)a * CR + k0 + ki) * CDIM + n0 + tx];
    }
    __syncthreads();
#pragma unroll
    for (int jj = 0; jj < 4; jj++) {
        int ni = ty + jj * 8;
        g_w2t[((long)a * CDIM + n0 + ni) * CR + k0 + tx] = __float2half_rn(t[tx][ni]);
    }
}
__global__ void fold_bias_part(const float* __restrict__ ln_bias, const float* __restrict__ w1) {
    int a = blockIdx.x, ch = blockIdx.y, d = threadIdx.x;
    const float* wb = w1 + (long)a * CDIM * CR + (long)ch * 32 * CR;
    const float* lb = ln_bias + a * CDIM + ch * 32;
    float s = 0.f;
#pragma unroll
    for (int c = 0; c < 32; c++) s = fmaf(lb[c], wb[(long)c * CR + d], s);
    g_bpart[ch][a * CR + d] = s;
}
__global__ void fold_bias_reduce() {
    int i = blockIdx.x * 256 + threadIdx.x;
    if (i >= NADP * CR) return;
    float s = 0.f;
#pragma unroll
    for (int ch = 0; ch < 32; ch++) s += g_bpart[ch][i];
    g_bias1[i] = s;
}

// ---------------- LayerNorm ----------------
__global__ void ln_stats_kernel(const float* __restrict__ feat) {
    int b  = blockIdx.y;
    int p0 = blockIdx.x * 32;
    int tx = threadIdx.x, ty = threadIdx.y;
    const float* base = feat + (long)b * CDIM * HWSZ + p0 + tx;
    float s = 0.f, sq = 0.f;
#pragma unroll 16
    for (int c = ty; c < CDIM; c += 8) {
        float v = base[(long)c * HWSZ];
        s += v; sq = fmaf(v, v, sq);
    }
    __shared__ float ss[8][33], qq[8][33];
    ss[ty][tx] = s; qq[ty][tx] = sq;
    __syncthreads();
    if (ty == 0) {
        float S = 0.f, Q = 0.f;
#pragma unroll
        for (int j = 0; j < 8; j++) { S += ss[j][tx]; Q += qq[j][tx]; }
        float mean = S * (1.0f / CDIM);
        float var  = Q * (1.0f / CDIM) - mean * mean;
        int tok = b * HWSZ + p0 + tx;
        g_mean[tok] = mean;
        g_rstd[tok] = rsqrtf(var + 1e-5f);
    }
}
__global__ void ln_apply_kernel(const float* __restrict__ feat) {
    __shared__ float t[32][33];
    int b  = blockIdx.z;
    int c0 = blockIdx.y * 32;
    int p0 = blockIdx.x * 32;
    int tx = threadIdx.x, ty = threadIdx.y;
#pragma unroll
    for (int cj = 0; cj < 4; cj++) {
        int ci = ty + cj * 8;
        t[ci][tx] = feat[((long)b * CDIM + c0 + ci) * HWSZ + p0 + tx];
    }
    __syncthreads();
#pragma unroll
    for (int pj = 0; pj < 4; pj++) {
        int pi = ty + pj * 8;
        int tok = b * HWSZ + p0 + pi;
        float mean = g_mean[tok], rstd = g_rstd[tok];
        g_norm[(long)tok * CDIM + c0 + tx] = __float2half_rn((t[tx][pi] - mean) * rstd);
    }
}

// ---------------- fp16 mma.sync GEMM: 128x128 CTA, 4 warps of 64x64, cp.async 3-stage ----------------
// Per-stage SMEM: A tile 128x32 half (8KB) + B tile (8KB) = 16KB. 64B rows,
// 16B-chunk swizzle: chunk' = chunk ^ ((row>>1)&3)  (conflict-free fills + frag loads).
#define G_STAGES   3
#define G_STAGE_B  16384
#define G_PTRS_B   2048
#define G_SMEM_TOTAL (G_PTRS_B + G_STAGES * G_STAGE_B)

// mode 1: gelu(x+bias) -> half store. mode 2: weighted fp32 atomic accum.
__global__ void __launch_bounds__(128, 2)
mma_gemm(const __half* __restrict__ Ab, const __half* __restrict__ Bb,
         const float* __restrict__ bias, __half* __restrict__ Cb,
         const int* __restrict__ tlA,
         const int* __restrict__ tlE,
         const float* __restrict__ wts,
         float* __restrict__ accumC,
         int K, int lda, int ldb, int ldc,
         long sA, long sB, long sC, int mode)
{
    extern __shared__ char smem[];
    int tid = threadIdx.x;
    int mB = blockIdx.x * 128, nB = blockIdx.y * 128, a = blockIdx.z;

    int cnt = g_cnt[a];
    if (mB >= cnt) return;

    const __half* A = Ab + (long)a * sA;
    const __half* B = Bb + (long)a * sB;
    __half* C = Cb + (long)a * sC;
    const int* tla = tlA ? tlA + a * NTOK : nullptr;

    const __half** sAp = (const __half**)smem;
    const __half** sBp = sAp + 128;
    uint32_t sm_base = smem_u32(smem) + G_PTRS_B;

    {
        int m = mB + tid;
        int mc = m < cnt ? m : (cnt - 1);
        long arow = tla ? (long)tla[mc] : (long)mc;
        sAp[tid] = A + arow * lda;
        sBp[tid] = B + (long)(nB + tid) * ldb;
    }
    __syncthreads();

    int lane = tid & 31, wid = tid >> 5;
    int wm0 = (wid & 1) * 64;
    int wn0 = (wid >> 1) * 64;
    int r = lane >> 2, c = lane & 3;

    int nkt = K >> 5;
    int kc = tid & 3;      // 16B chunk (8 halves) within 64B row
    int r0 = tid >> 2;     // 0..31

#define FILL_STAGE(sidx, k0)  do {                                             \
        uint32_t base = sm_base + (sidx) * G_STAGE_B;                          \
        _Pragma("unroll")                                                      \
        for (int i = 0; i < 4; i++) {                                          \
            int row = r0 + i * 32;                                             \
            uint32_t off = (uint32_t)(row * 64 + ((kc ^ ((row >> 1) & 3)) << 4)); \
            cp16(base + off, sAp[row] + (k0) + kc * 8);                        \
            cp16(base + 8192 + off, sBp[row] + (k0) + kc * 8);                 \
        }                                                                      \
        CP_COMMIT();                                                           \
    } while (0)

    float acc[4][8][4];
#pragma unroll
    for (int t = 0; t < 4; t++)
#pragma unroll
        for (int u = 0; u < 8; u++)
#pragma unroll
            for (int e = 0; e < 4; e++) acc[t][u][e] = 0.f;

    FILL_STAGE(0, 0);
    FILL_STAGE(1, 32);
    CP_WAIT(1);
    __syncthreads();

    for (int kt = 0; kt < nkt; kt++) {
        const char* As = smem + G_PTRS_B + (kt % 3) * G_STAGE_B;
        const char* Bs = As + 8192;

#pragma unroll
        for (int j = 0; j < 2; j++) {
            uint32_t bf[8][2];
#pragma unroll
            for (int u = 0; u < 8; u++) {
                int n = wn0 + u * 8 + r;
                bf[u][0] = lds_u32(Bs, n, 2 * j,     c);
                bf[u][1] = lds_u32(Bs, n, 2 * j + 1, c);
            }
#pragma unroll
            for (int t = 0; t < 4; t++) {
                int m0 = wm0 + t * 16 + r;
                uint32_t a0 = lds_u32(As, m0,     2 * j,     c);
                uint32_t a1 = lds_u32(As, m0 + 8, 2 * j,     c);
                uint32_t a2 = lds_u32(As, m0,     2 * j + 1, c);
                uint32_t a3 = lds_u32(As, m0 + 8, 2 * j + 1, c);
#pragma unroll
                for (int u = 0; u < 8; u++)
                    mma_f16(acc[t][u], a0, a1, a2, a3, bf[u][0], bf[u][1]);
            }
        }

        if (kt + 2 < nkt) {
            __syncthreads();
            FILL_STAGE((kt + 2) % 3, (kt + 2) * 32);
            CP_WAIT(1);
            __syncthreads();
        } else if (kt + 1 < nkt) {
            CP_WAIT(0);
            __syncthreads();
        }
    }

    // ---- epilogue ----
    if (mode == 2) {
        const int* tle = tlE + a * NTOK;
        const float* wta = wts + a * NTOK;
#pragma unroll
        for (int t = 0; t < 4; t++) {
            int gr0 = mB + wm0 + t * 16 + r;
            int gr1 = gr0 + 8;
            bool k0 = gr0 < cnt;
            bool k1 = gr1 < cnt;
            if (!k0 && !k1) continue;
            long t0 = k0 ? (long)tle[gr0] : 0;
            long t1 = k1 ? (long)tle[gr1] : 0;
            float w0 = k0 ? wta[gr0] : 0.f;
            float w1v = k1 ? wta[gr1] : 0.f;
            float* d0 = accumC + t0 * CDIM;
            float* d1 = accumC + t1 * CDIM;
#pragma unroll
            for (int u = 0; u < 8; u++) {
                int col = nB + wn0 + u * 8 + c * 2;
                if (k0) {
                    atomicAdd(d0 + col,     acc[t][u][0] * w0);
                    atomicAdd(d0 + col + 1, acc[t][u][1] * w0);
                }
                if (k1) {
                    atomicAdd(d1 + col,     acc[t][u][2] * w1v);
                    atomicAdd(d1 + col + 1, acc[t][u][3] * w1v);
                }
            }
        }
    } else {
#pragma unroll
        for (int t = 0; t < 4; t++) {
            int gr0 = mB + wm0 + t * 16 + r;
            int gr1 = gr0 + 8;
            bool k0 = gr0 < cnt;
            bool k1 = gr1 < cnt;
            if (!k0 && !k1) continue;
#pragma unroll
            for (int u = 0; u < 8; u++) {
                int col = nB + wn0 + u * 8 + c * 2;
                float b0v = bias[a * CR + col], b1v = bias[a * CR + col + 1];
                float v00 = gelu_exact(acc[t][u][0] + b0v);
                float v01 = gelu_exact(acc[t][u][1] + b1v);
                float v10 = gelu_exact(acc[t][u][2] + b0v);
                float v11 = gelu_exact(acc[t][u][3] + b1v);
                if (k0) *(__half2*)(C + (long)gr0 * ldc + col) =
                    __halves2half2(__float2half_rn(v00), __float2half_rn(v01));
                if (k1) *(__half2*)(C + (long)gr1 * ldc + col) =
                    __halves2half2(__float2half_rn(v10), __float2half_rn(v11));
            }
        }
    }
#undef FILL_STAGE
}

// ---------------- final: out = accum + feat, NCHW ----------------
__global__ void final_kernel(const float* __restrict__ feat, float* __restrict__ out) {
    __shared__ float t[32][33];
    int b  = blockIdx.z;
    int c0 = blockIdx.y * 32;
    int p0 = blockIdx.x * 32;
    int tx = threadIdx.x, ty = threadIdx.y;
#pragma unroll
    for (int pj = 0; pj < 4; pj++) {
        int pi = ty + pj * 8;
        long tok = (long)b * HWSZ + p0 + pi;
        t[pi][tx] = g_accum[tok * CDIM + c0 + tx];
    }
    __syncthreads();
    int tid = ty * 32 + tx;
    int pi  = tid & 31;
    int ci0 = tid >> 5;
#pragma unroll
    for (int cj = 0; cj < 4; cj++) {
        int ci = ci0 + cj * 8;
        long off = (long)(b * CDIM + c0 + ci) * HWSZ + p0 + pi;
        out[off] = t[pi][ci] + feat[off];
    }
}

// ---------------- launch ----------------
extern "C" void kernel_launch(void* const* d_in, const int* in_sizes, int n_in,
                              void* d_out, int out_size) {
    const float* feat     = (const float*)d_in[0];
    const float* ar       = (const float*)d_in[1];
    const float* ln_scale = (const float*)d_in[2];
    const float* ln_bias  = (const float*)d_in[3];
    const float* w1       = (const float*)d_in[4];
    const float* w2       = (const float*)d_in[5];
    float* out = (float*)d_out;

    __half *norm, *w1t, *w2t, *h;
    float *bias1, *accum, *wt;
    int *toklist;
    cudaGetSymbolAddress((void**)&norm,    g_norm);
    cudaGetSymbolAddress((void**)&w1t,     g_w1t);
    cudaGetSymbolAddress((void**)&w2t,     g_w2t);
    cudaGetSymbolAddress((void**)&bias1,   g_bias1);
    cudaGetSymbolAddress((void**)&h,       g_h);
    cudaGetSymbolAddress((void**)&accum,   g_accum);
    cudaGetSymbolAddress((void**)&toklist, g_toklist);
    cudaGetSymbolAddress((void**)&wt,      g_wt);

    static bool attr_set = false;
    if (!attr_set) {
        cudaFuncSetAttribute(mma_gemm, cudaFuncAttributeMaxDynamicSharedMemorySize, G_SMEM_TOTAL);
        attr_set = true;
    }

    cudaMemsetAsync(accum, 0, (long)NTOK * CDIM * sizeof(float));
    zero_cnt_kernel<<<1, 32>>>();
    compact_kernel<<<NTOK / 256, 256>>>(ar);
    prep_w1_kernel<<<dim3(CDIM / 32, CR / 32, NADP), dim3(32, 8)>>>(ln_scale, w1);
    prep_w2_kernel<<<dim3(CDIM / 32, CR / 32, NADP), dim3(32, 8)>>>(w2);
    fold_bias_part<<<dim3(NADP, 32), 256>>>(ln_bias, w1);
    fold_bias_reduce<<<(NADP * CR + 255) / 256, 256>>>();
    ln_stats_kernel<<<dim3(HWSZ / 32, BBAT), dim3(32, 8)>>>(feat);
    ln_apply_kernel<<<dim3(HWSZ / 32, CDIM / 32, BBAT), dim3(32, 8)>>>(feat);

    // GEMM1 (mode 1): h[a][slot] = gelu(norm[tok(slot)] @ w1t[a]^T + bias1[a])
    mma_gemm<<<dim3(NTOK / 128, CR / 128, NADP), 128, G_SMEM_TOTAL>>>(
        norm, w1t, bias1, h, toklist, nullptr, nullptr, nullptr,
        CDIM, CDIM, CDIM, CR,
        0L, (long)CR * CDIM, (long)NTOK * CR, 1);

    // GEMM2 (mode 2): accum[tok] += w * (h[a][slot] @ w2t[a]^T)
    mma_gemm<<<dim3(NTOK / 128, CDIM / 128, NADP), 128, G_SMEM_TOTAL>>>(
        h, w2t, nullptr, nullptr, nullptr, toklist, wt, accum,
        CR, CR, CR, CDIM,
        (long)NTOK * CR, (long)CDIM * CR, 0L, 2);

    // final: out = accum + feat (NCHW)
    final_kernel<<<dim3(HWSZ / 32, CDIM / 32, BBAT), dim3(32, 8)>>>(feat, out);
}